// round 12
// baseline (speedup 1.0000x reference)
#include <cuda_runtime.h>
#include <cuda_bf16.h>
#include <math.h>
#include <stdint.h>

// Shapes (fixed by setup_inputs)
#define B_  4
#define C_  64
#define H_  128
#define W_  128
#define HW  (H_*W_)          // 16384
#define OCF 576              // f_conv output channels = C*9
#define KTOT 576             // 64*9 reduction size

// Scratch (__device__ globals: allocation-free rule)
__device__ float g_off[B_ * 18 * HW];
__device__ float g_m[B_ * 9 * HW];
// interleaved bf16-split weights: uint2 {hi_pair, lo_pair} at [(s*32+icp)*OCF + oc]
__device__ uint2 g_w2[9 * 32 * OCF];
// sampling tables: per (bh, t, w): packed coords (u8, +1 bias) + 4 weights*m
__device__ uint32_t g_tabc[512 * 9 * 128];
__device__ float4   g_tabg[512 * 9 * 128];

__device__ __forceinline__ uint32_t pack_bf16(__nv_bfloat16 lo, __nv_bfloat16 hi) {
    uint32_t l = (uint32_t)__bfloat16_as_ushort(lo);
    uint32_t h = (uint32_t)__bfloat16_as_ushort(hi);
    return l | (h << 16);
}

__device__ __forceinline__ void mma_bf16(float* c,
        uint32_t a0, uint32_t a1, uint32_t a2, uint32_t a3,
        uint32_t b0, uint32_t b1) {
    asm volatile(
        "mma.sync.aligned.m16n8k16.row.col.f32.bf16.bf16.f32 "
        "{%0,%1,%2,%3}, {%4,%5,%6,%7}, {%8,%9}, {%0,%1,%2,%3};"
        : "+f"(c[0]), "+f"(c[1]), "+f"(c[2]), "+f"(c[3])
        : "r"(a0), "r"(a1), "r"(a2), "r"(a3), "r"(b0), "r"(b1));
}

// ---------------------------------------------------------------------------
// K0: split f_conv_w into bf16 hi/lo, ic-pair packed, hi/lo interleaved uint2.
// ---------------------------------------------------------------------------
__global__ void weight_split_kernel(const float* __restrict__ wgt) {
    int idx = blockIdx.x * blockDim.x + threadIdx.x;   // over 9*32*576
    if (idx >= 9 * 32 * OCF) return;
    int oc = idx % OCF;
    int tmp = idx / OCF;
    int icp = tmp & 31;
    int s = tmp >> 5;
    float w0 = wgt[oc * KTOT + (2 * icp) * 9 + s];
    float w1 = wgt[oc * KTOT + (2 * icp + 1) * 9 + s];
    __nv_bfloat16 h0 = __float2bfloat16(w0);
    __nv_bfloat16 h1 = __float2bfloat16(w1);
    __nv_bfloat16 l0 = __float2bfloat16(w0 - __bfloat162float(h0));
    __nv_bfloat16 l1 = __float2bfloat16(w1 - __bfloat162float(h1));
    g_w2[idx] = make_uint2(pack_bf16(h0, h1), pack_bf16(l0, l1));
}

// ---------------------------------------------------------------------------
// K1: merged small conv3x3: 27 outputs = 18 offset channels + 9 mask (sigmoid).
// ---------------------------------------------------------------------------
#define OCM  27
#define OCMP 28
__global__ void conv_small_merged_kernel(const float* __restrict__ in,
                                         const float* __restrict__ p_w,
                                         const float* __restrict__ p_b,
                                         const float* __restrict__ m_w,
                                         const float* __restrict__ m_b) {
    const int bh = blockIdx.x;
    const int b = bh >> 7;
    const int h = bh & 127;
    const int tid = threadIdx.x;      // 128 threads, tid == w
    const int w = tid;

    __shared__ __align__(16) float sIn[16 * 3 * 132];
    __shared__ __align__(16) float sW[144 * OCMP];

    float acc[OCMP];
#pragma unroll
    for (int i = 0; i < OCMP; i++) acc[i] = 0.f;

    const float* inb = in + b * C_ * HW;

    for (int chunk = 0; chunk < 4; chunk++) {
        for (int idx = tid; idx < 144 * OCMP; idx += 128) sW[idx] = 0.f;
        __syncthreads();
        for (int idx = tid; idx < 16 * 3 * 130; idx += 128) {
            int ic = idx / 390;
            int rem = idx - ic * 390;
            int r = rem / 130;
            int cc = rem - r * 130;
            int gh = h + r - 1;
            int gw = cc - 1;
            float v = 0.f;
            if ((unsigned)gh < 128u && (unsigned)gw < 128u)
                v = inb[(chunk * 16 + ic) * HW + gh * 128 + gw];
            sIn[(ic * 3 + r) * 132 + cc] = v;
        }
        for (int idx = tid; idx < 144 * OCM; idx += 128) {
            int oc = idx / 144;
            int k = idx - oc * 144;
            float wv = (oc < 18) ? p_w[oc * KTOT + chunk * 144 + k]
                                 : m_w[(oc - 18) * KTOT + chunk * 144 + k];
            sW[k * OCMP + oc] = wv;
        }
        __syncthreads();

#pragma unroll 4
        for (int ic = 0; ic < 16; ic++) {
#pragma unroll
            for (int r = 0; r < 3; r++) {
                float v0 = sIn[(ic * 3 + r) * 132 + w];
                float v1 = sIn[(ic * 3 + r) * 132 + w + 1];
                float v2 = sIn[(ic * 3 + r) * 132 + w + 2];
#pragma unroll
                for (int dw = 0; dw < 3; dw++) {
                    float v = (dw == 0) ? v0 : ((dw == 1) ? v1 : v2);
                    const float4* wp = (const float4*)&sW[(ic * 9 + r * 3 + dw) * OCMP];
#pragma unroll
                    for (int o4 = 0; o4 < OCMP / 4; o4++) {
                        float4 wv = wp[o4];
                        acc[o4 * 4 + 0] += v * wv.x;
                        acc[o4 * 4 + 1] += v * wv.y;
                        acc[o4 * 4 + 2] += v * wv.z;
                        acc[o4 * 4 + 3] += v * wv.w;
                    }
                }
            }
        }
        __syncthreads();
    }

#pragma unroll
    for (int oc = 0; oc < 18; oc++)
        g_off[((b * 18 + oc) * 128 + h) * 128 + w] = acc[oc] + p_b[oc];
#pragma unroll
    for (int oc = 0; oc < 9; oc++) {
        float v = acc[18 + oc] + m_b[oc];
        g_m[((b * 9 + oc) * 128 + h) * 128 + w] = 1.f / (1.f + expf(-v));
    }
}

// ---------------------------------------------------------------------------
// K_samp: per (b,h,w,t) sampling table.
// ---------------------------------------------------------------------------
__global__ __launch_bounds__(256) void samp_table_kernel() {
    const int bh = blockIdx.x;
    const int b = bh >> 7;
    const int h = bh & 127;
    const int tid = threadIdx.x;

    for (int item = tid; item < 9 * 128; item += 256) {
        int t = item >> 7;
        int w = item & 127;
        int i = t / 3, j = t - 3 * i;
        int hp = (i == 0) ? h - 1 : h;
        int ip = (i == 0) ? 2 : i - 1;
        int wp = (j == 0) ? w - 1 : w;
        int jp = (j == 0) ? 2 : j - 1;
        uint32_t pc = 0;
        float4 g4 = make_float4(0.f, 0.f, 0.f, 0.f);
        if (hp >= 0 && wp >= 0) {
            int k = ip * 3 + jp;
            float dxk = (float)(ip - 1);
            float dyk = (float)(jp - 1);
            int obase = ((b * 18 + k) * 128 + hp) * 128 + wp;
            float ox = g_off[obase];
            float oy = g_off[obase + 9 * HW];
            float px = (float)(hp + 1) + dxk + ox;
            float py = (float)(wp + 1) + dyk + oy;
            float fx = floorf(px), fy = floorf(py);
            float ltx = fminf(fmaxf(fx, 0.f), 129.f);
            float lty = fminf(fmaxf(fy, 0.f), 129.f);
            float rbx = fminf(fmaxf(fx + 1.f, 0.f), 129.f);
            float rby = fminf(fmaxf(fy + 1.f, 0.f), 129.f);
            float pxc = fminf(fmaxf(px, 0.f), 129.f);
            float pyc = fminf(fmaxf(py, 0.f), 129.f);
            float gxl = 1.f + (ltx - pxc);
            float gxr = 1.f - (rbx - pxc);
            float gyl = 1.f + (lty - pyc);
            float gyr = 1.f - (rby - pyc);
            float mv = g_m[((b * 9 + k) * 128 + hp) * 128 + wp];
            uint32_t axs = (uint32_t)(int)ltx;     // 0..129
            uint32_t ays = (uint32_t)(int)lty;
            uint32_t bxs = (uint32_t)(int)rbx;
            uint32_t bys = (uint32_t)(int)rby;
            pc = axs | (ays << 8) | (bxs << 16) | (bys << 24);
            g4 = make_float4(gxl * gyl * mv, gxr * gyr * mv,
                             gxl * gyr * mv, gxr * gyl * mv);
        }
        g_tabc[bh * 1152 + t * 128 + w] = pc;
        g_tabg[bh * 1152 + t * 128 + w] = g4;
    }
}

// ---------------------------------------------------------------------------
// K2-fused: psff conv (bf16-split tensor-core implicit GEMM) + deformable
// sampling reduction.
// Grid: (8 oc-tiles of 72, 512 bh rows). 128 threads, warp tile 32px x 72oc.
// B staged in smem per 3-tap phase (B identical across all 4 warps ->
// staging cuts B L1 wavefronts ~4-5x vs scattered per-warp LDG.32).
// A and B tiles hi/lo interleaved uint2; all fragment LDS.64 conflict-free.
// ---------------------------------------------------------------------------
#define SA_RSTRIDE 132                // uint2 per (r,icp) row
#define SB_RSTRIDE 76                 // uint2 per kp row (72 + 4 pad)
#define SA_SIZE (24 * SA_RSTRIDE)     // 3168 uint2
#define SB_SIZE (24 * SB_RSTRIDE)     // 1824 uint2 (3 taps x 8 icp)
#define SP_STRIDE 132

__global__ __launch_bounds__(128, 4) void conv_fused_kernel(
        const float* __restrict__ in,
        const float* __restrict__ bias,
        const float* __restrict__ x,
        float* __restrict__ out) {
    const int oc0 = blockIdx.x * 72;
    const int bh = blockIdx.y;
    const int b = bh >> 7;
    const int h = bh & 127;
    const int tid = threadIdx.x;
    const int warp = tid >> 5;                // 0..3
    const int lane = tid & 31;
    const int g = lane >> 2;                  // 0..7
    const int t = lane & 3;                   // 0..3
    const int px0 = warp * 32;

    // smem: sA (3168 uint2) + sB (1824 uint2) = 39.9 KB; epilogue aliases sP.
    __shared__ __align__(16) uint2 sBuf2[SA_SIZE + SB_SIZE];
    uint2* sA2 = sBuf2;
    uint2* sB2 = sBuf2 + SA_SIZE;
    float* sP = (float*)sBuf2;

    float acc[2][9][4];
#pragma unroll
    for (int mt = 0; mt < 2; mt++)
#pragma unroll
        for (int nt = 0; nt < 9; nt++)
#pragma unroll
            for (int q = 0; q < 4; q++) acc[mt][nt][q] = 0.f;

    const float* inb = in + b * C_ * HW;

    for (int chunk = 0; chunk < 4; chunk++) {
        __syncthreads();
        // stage A: 8 ic-pairs x 3 rows x 130 cols, hi/lo interleaved uint2
        for (int idx = tid; idx < 8 * 3 * 130; idx += 128) {
            int icp = idx / 390;
            int rem = idx - icp * 390;
            int r = rem / 130;
            int cc = rem - r * 130;
            int gh = h + r - 1;
            int gw = cc - 1;
            float v0 = 0.f, v1 = 0.f;
            if ((unsigned)gh < 128u && (unsigned)gw < 128u) {
                const float* p = inb + (chunk * 16 + 2 * icp) * HW + gh * 128 + gw;
                v0 = p[0];
                v1 = p[HW];
            }
            __nv_bfloat16 h0 = __float2bfloat16(v0);
            __nv_bfloat16 h1 = __float2bfloat16(v1);
            __nv_bfloat16 l0 = __float2bfloat16(v0 - __bfloat162float(h0));
            __nv_bfloat16 l1 = __float2bfloat16(v1 - __bfloat162float(h1));
            sA2[(r * 8 + icp) * SA_RSTRIDE + cc] =
                make_uint2(pack_bf16(h0, h1), pack_bf16(l0, l1));
        }

#pragma unroll
        for (int phase = 0; phase < 3; phase++) {
            if (phase > 0) __syncthreads();   // prior-phase B reads done
            // stage B phase: taps [phase*3, phase*3+3) -> 24 rows x 72 uint2
            for (int idx = tid; idx < 24 * 72; idx += 128) {
                int rl = idx / 72;
                int col = idx - rl * 72;
                int s = phase * 3 + (rl >> 3);
                int icp = rl & 7;
                int kp = s * 32 + chunk * 8 + icp;
                sB2[rl * SB_RSTRIDE + col] = g_w2[kp * OCF + oc0 + col];
            }
            __syncthreads();

#pragma unroll
            for (int tl = 0; tl < 3; tl++) {
                const int s = phase * 3 + tl;
                const int r = s / 3;
                const int dw = s - 3 * r;

                // A fragments for 2 m-tiles, hi + lo (LDS.64, conflict-free)
                uint32_t ah[2][4], al[2][4];
#pragma unroll
                for (int mt = 0; mt < 2; mt++) {
                    int cb = px0 + mt * 16 + g + dw;
                    int base_lo = (r * 8 + t) * SA_RSTRIDE + cb;
                    int base_hi = (r * 8 + t + 4) * SA_RSTRIDE + cb;
                    uint2 q0 = sA2[base_lo];
                    uint2 q1 = sA2[base_lo + 8];
                    uint2 q2 = sA2[base_hi];
                    uint2 q3 = sA2[base_hi + 8];
                    ah[mt][0] = q0.x; al[mt][0] = q0.y;
                    ah[mt][1] = q1.x; al[mt][1] = q1.y;
                    ah[mt][2] = q2.x; al[mt][2] = q2.y;
                    ah[mt][3] = q3.x; al[mt][3] = q3.y;
                }

                // n-tiles in groups of 3; B from smem (LDS.64, conflict-free)
#pragma unroll
                for (int ntg = 0; ntg < 3; ntg++) {
                    uint2 p0[3], p1[3];
#pragma unroll
                    for (int u = 0; u < 3; u++) {
                        int col = (ntg * 3 + u) * 8 + g;
                        p0[u] = sB2[(tl * 8 + t) * SB_RSTRIDE + col];
                        p1[u] = sB2[(tl * 8 + t + 4) * SB_RSTRIDE + col];
                    }
#pragma unroll
                    for (int u = 0; u < 3; u++) {
#pragma unroll
                        for (int mt = 0; mt < 2; mt++) {
                            float* a = acc[mt][ntg * 3 + u];
                            mma_bf16(a, ah[mt][0], ah[mt][1], ah[mt][2], ah[mt][3], p0[u].x, p1[u].x);
                            mma_bf16(a, ah[mt][0], ah[mt][1], ah[mt][2], ah[mt][3], p0[u].y, p1[u].y);
                            mma_bf16(a, al[mt][0], al[mt][1], al[mt][2], al[mt][3], p0[u].x, p1[u].x);
                        }
                    }
                }
            }
        }
    }

    // ---- epilogue phase 1: accumulators (+bias) -> sP[oc_local][px] ----
    __syncthreads();
#pragma unroll
    for (int nt = 0; nt < 9; nt++) {
        int oc_l = nt * 8 + 2 * t;
        float bva = __ldg(&bias[oc0 + oc_l]);
        float bvb = __ldg(&bias[oc0 + oc_l + 1]);
#pragma unroll
        for (int mt = 0; mt < 2; mt++) {
            int px = px0 + mt * 16 + g;
            sP[oc_l * SP_STRIDE + px]           = acc[mt][nt][0] + bva;
            sP[(oc_l + 1) * SP_STRIDE + px]     = acc[mt][nt][1] + bvb;
            sP[oc_l * SP_STRIDE + px + 8]       = acc[mt][nt][2] + bva;
            sP[(oc_l + 1) * SP_STRIDE + px + 8] = acc[mt][nt][3] + bvb;
        }
    }
    __syncthreads();

    // ---- epilogue phase 2: sampling reduction, 8 channels per thread ----
    const int w = tid;                         // 0..127
    const int c0 = blockIdx.x << 3;            // global channel base
    const float* xb = x + (size_t)(b * C_ + c0) * HW;

    float val[8] = {0.f, 0.f, 0.f, 0.f, 0.f, 0.f, 0.f, 0.f};

#pragma unroll
    for (int tt = 0; tt < 9; tt++) {
        uint32_t pc = g_tabc[bh * 1152 + tt * 128 + w];
        float4 g4 = g_tabg[bh * 1152 + tt * 128 + w];
        int ax = (int)(pc & 255u) - 1;
        int ay = (int)((pc >> 8) & 255u) - 1;
        int bx = (int)((pc >> 16) & 255u) - 1;
        int by = (int)(pc >> 24) - 1;
        bool vax = (unsigned)ax < 128u, vay = (unsigned)ay < 128u;
        bool vbx = (unsigned)bx < 128u, vby = (unsigned)by < 128u;
        int id0 = ax * 128 + ay;   // lt
        int id1 = bx * 128 + by;   // rb
        int id2 = ax * 128 + by;   // lb
        int id3 = bx * 128 + ay;   // rt
        const float* ps = &sP[tt * SP_STRIDE + w];
#pragma unroll
        for (int c = 0; c < 8; c++) {
            const float* xpl = xb + (size_t)c * HW;
            float s = 0.f;
            if (vax && vay) s += g4.x * __ldg(xpl + id0);
            if (vbx && vby) s += g4.y * __ldg(xpl + id1);
            if (vax && vby) s += g4.z * __ldg(xpl + id2);
            if (vbx && vay) s += g4.w * __ldg(xpl + id3);
            val[c] += s * ps[c * 9 * SP_STRIDE];
        }
    }

    float* ob = out + (size_t)(b * C_ + c0) * HW + h * 128 + w;
#pragma unroll
    for (int c = 0; c < 8; c++)
        ob[(size_t)c * HW] = val[c];
}

// ---------------------------------------------------------------------------
extern "C" void kernel_launch(void* const* d_in, const int* in_sizes, int n_in,
                              void* d_out, int out_size) {
    const float* feature_size    = (const float*)d_in[0];
    const float* feature_context = (const float*)d_in[1];
    const float* x               = (const float*)d_in[2];
    const float* p_conv_w        = (const float*)d_in[3];
    const float* p_conv_b        = (const float*)d_in[4];
    const float* f_conv_w        = (const float*)d_in[5];
    const float* f_conv_b        = (const float*)d_in[6];
    const float* m_conv_w        = (const float*)d_in[7];
    const float* m_conv_b        = (const float*)d_in[8];
    float* out = (float*)d_out;

    // K0: split/pack f_conv_w to interleaved bf16 hi/lo
    weight_split_kernel<<<(9 * 32 * OCF + 255) / 256, 256>>>(f_conv_w);

    // K1: merged offset(18) + mask(9, sigmoid) conv
    conv_small_merged_kernel<<<B_ * H_, 128>>>(feature_size, p_conv_w, p_conv_b,
                                               m_conv_w, m_conv_b);

    // K_samp: sampling tables from g_off/g_m
    samp_table_kernel<<<B_ * H_, 256>>>();

    // K2-fused: psff conv + sampling reduction -> out
    dim3 grid2(8, B_ * H_);
    conv_fused_kernel<<<grid2, 128>>>(feature_context, f_conv_b, x, out);
}

// round 13
// speedup vs baseline: 1.0641x; 1.0641x over previous
#include <cuda_runtime.h>
#include <cuda_bf16.h>
#include <math.h>
#include <stdint.h>

// Shapes (fixed by setup_inputs)
#define B_  4
#define C_  64
#define H_  128
#define W_  128
#define HW  (H_*W_)          // 16384
#define OCF 576              // f_conv output channels = C*9
#define KTOT 576             // 64*9 reduction size

// Scratch (__device__ globals: allocation-free rule)
__device__ float g_off[B_ * 18 * HW];
__device__ float g_m[B_ * 9 * HW];
// interleaved bf16-split weights: uint2 {hi_pair, lo_pair} at [(s*32+icp)*OCF + oc]
__device__ uint2 g_w2[9 * 32 * OCF];
// sampling tables: per (bh, t, w): packed coords (u8, +1 bias) + 4 weights*m
__device__ uint32_t g_tabc[512 * 9 * 128];
__device__ float4   g_tabg[512 * 9 * 128];

__device__ __forceinline__ uint32_t pack_bf16(__nv_bfloat16 lo, __nv_bfloat16 hi) {
    uint32_t l = (uint32_t)__bfloat16_as_ushort(lo);
    uint32_t h = (uint32_t)__bfloat16_as_ushort(hi);
    return l | (h << 16);
}

__device__ __forceinline__ void mma_bf16(float* c,
        uint32_t a0, uint32_t a1, uint32_t a2, uint32_t a3,
        uint32_t b0, uint32_t b1) {
    asm volatile(
        "mma.sync.aligned.m16n8k16.row.col.f32.bf16.bf16.f32 "
        "{%0,%1,%2,%3}, {%4,%5,%6,%7}, {%8,%9}, {%0,%1,%2,%3};"
        : "+f"(c[0]), "+f"(c[1]), "+f"(c[2]), "+f"(c[3])
        : "r"(a0), "r"(a1), "r"(a2), "r"(a3), "r"(b0), "r"(b1));
}

// ---------------------------------------------------------------------------
// K0: split f_conv_w into bf16 hi/lo, ic-pair packed, hi/lo interleaved uint2.
// ---------------------------------------------------------------------------
__global__ void weight_split_kernel(const float* __restrict__ wgt) {
    int idx = blockIdx.x * blockDim.x + threadIdx.x;   // over 9*32*576
    if (idx >= 9 * 32 * OCF) return;
    int oc = idx % OCF;
    int tmp = idx / OCF;
    int icp = tmp & 31;
    int s = tmp >> 5;
    float w0 = wgt[oc * KTOT + (2 * icp) * 9 + s];
    float w1 = wgt[oc * KTOT + (2 * icp + 1) * 9 + s];
    __nv_bfloat16 h0 = __float2bfloat16(w0);
    __nv_bfloat16 h1 = __float2bfloat16(w1);
    __nv_bfloat16 l0 = __float2bfloat16(w0 - __bfloat162float(h0));
    __nv_bfloat16 l1 = __float2bfloat16(w1 - __bfloat162float(h1));
    g_w2[idx] = make_uint2(pack_bf16(h0, h1), pack_bf16(l0, l1));
}

// ---------------------------------------------------------------------------
// K1: merged small conv3x3: 27 outputs = 18 offset channels + 9 mask (sigmoid).
// ---------------------------------------------------------------------------
#define OCM  27
#define OCMP 28
__global__ void conv_small_merged_kernel(const float* __restrict__ in,
                                         const float* __restrict__ p_w,
                                         const float* __restrict__ p_b,
                                         const float* __restrict__ m_w,
                                         const float* __restrict__ m_b) {
    const int bh = blockIdx.x;
    const int b = bh >> 7;
    const int h = bh & 127;
    const int tid = threadIdx.x;      // 128 threads, tid == w
    const int w = tid;

    __shared__ __align__(16) float sIn[16 * 3 * 132];
    __shared__ __align__(16) float sW[144 * OCMP];

    float acc[OCMP];
#pragma unroll
    for (int i = 0; i < OCMP; i++) acc[i] = 0.f;

    const float* inb = in + b * C_ * HW;

    for (int chunk = 0; chunk < 4; chunk++) {
        for (int idx = tid; idx < 144 * OCMP; idx += 128) sW[idx] = 0.f;
        __syncthreads();
        for (int idx = tid; idx < 16 * 3 * 130; idx += 128) {
            int ic = idx / 390;
            int rem = idx - ic * 390;
            int r = rem / 130;
            int cc = rem - r * 130;
            int gh = h + r - 1;
            int gw = cc - 1;
            float v = 0.f;
            if ((unsigned)gh < 128u && (unsigned)gw < 128u)
                v = inb[(chunk * 16 + ic) * HW + gh * 128 + gw];
            sIn[(ic * 3 + r) * 132 + cc] = v;
        }
        for (int idx = tid; idx < 144 * OCM; idx += 128) {
            int oc = idx / 144;
            int k = idx - oc * 144;
            float wv = (oc < 18) ? p_w[oc * KTOT + chunk * 144 + k]
                                 : m_w[(oc - 18) * KTOT + chunk * 144 + k];
            sW[k * OCMP + oc] = wv;
        }
        __syncthreads();

#pragma unroll 4
        for (int ic = 0; ic < 16; ic++) {
#pragma unroll
            for (int r = 0; r < 3; r++) {
                float v0 = sIn[(ic * 3 + r) * 132 + w];
                float v1 = sIn[(ic * 3 + r) * 132 + w + 1];
                float v2 = sIn[(ic * 3 + r) * 132 + w + 2];
#pragma unroll
                for (int dw = 0; dw < 3; dw++) {
                    float v = (dw == 0) ? v0 : ((dw == 1) ? v1 : v2);
                    const float4* wp = (const float4*)&sW[(ic * 9 + r * 3 + dw) * OCMP];
#pragma unroll
                    for (int o4 = 0; o4 < OCMP / 4; o4++) {
                        float4 wv = wp[o4];
                        acc[o4 * 4 + 0] += v * wv.x;
                        acc[o4 * 4 + 1] += v * wv.y;
                        acc[o4 * 4 + 2] += v * wv.z;
                        acc[o4 * 4 + 3] += v * wv.w;
                    }
                }
            }
        }
        __syncthreads();
    }

#pragma unroll
    for (int oc = 0; oc < 18; oc++)
        g_off[((b * 18 + oc) * 128 + h) * 128 + w] = acc[oc] + p_b[oc];
#pragma unroll
    for (int oc = 0; oc < 9; oc++) {
        float v = acc[18 + oc] + m_b[oc];
        g_m[((b * 9 + oc) * 128 + h) * 128 + w] = 1.f / (1.f + expf(-v));
    }
}

// ---------------------------------------------------------------------------
// K_samp: per (b,h,w,t) sampling table.
// ---------------------------------------------------------------------------
__global__ __launch_bounds__(256) void samp_table_kernel() {
    const int bh = blockIdx.x;
    const int b = bh >> 7;
    const int h = bh & 127;
    const int tid = threadIdx.x;

    for (int item = tid; item < 9 * 128; item += 256) {
        int t = item >> 7;
        int w = item & 127;
        int i = t / 3, j = t - 3 * i;
        int hp = (i == 0) ? h - 1 : h;
        int ip = (i == 0) ? 2 : i - 1;
        int wp = (j == 0) ? w - 1 : w;
        int jp = (j == 0) ? 2 : j - 1;
        uint32_t pc = 0;
        float4 g4 = make_float4(0.f, 0.f, 0.f, 0.f);
        if (hp >= 0 && wp >= 0) {
            int k = ip * 3 + jp;
            float dxk = (float)(ip - 1);
            float dyk = (float)(jp - 1);
            int obase = ((b * 18 + k) * 128 + hp) * 128 + wp;
            float ox = g_off[obase];
            float oy = g_off[obase + 9 * HW];
            float px = (float)(hp + 1) + dxk + ox;
            float py = (float)(wp + 1) + dyk + oy;
            float fx = floorf(px), fy = floorf(py);
            float ltx = fminf(fmaxf(fx, 0.f), 129.f);
            float lty = fminf(fmaxf(fy, 0.f), 129.f);
            float rbx = fminf(fmaxf(fx + 1.f, 0.f), 129.f);
            float rby = fminf(fmaxf(fy + 1.f, 0.f), 129.f);
            float pxc = fminf(fmaxf(px, 0.f), 129.f);
            float pyc = fminf(fmaxf(py, 0.f), 129.f);
            float gxl = 1.f + (ltx - pxc);
            float gxr = 1.f - (rbx - pxc);
            float gyl = 1.f + (lty - pyc);
            float gyr = 1.f - (rby - pyc);
            float mv = g_m[((b * 9 + k) * 128 + hp) * 128 + wp];
            uint32_t axs = (uint32_t)(int)ltx;     // 0..129
            uint32_t ays = (uint32_t)(int)lty;
            uint32_t bxs = (uint32_t)(int)rbx;
            uint32_t bys = (uint32_t)(int)rby;
            pc = axs | (ays << 8) | (bxs << 16) | (bys << 24);
            g4 = make_float4(gxl * gyl * mv, gxr * gyr * mv,
                             gxl * gyr * mv, gxr * gyl * mv);
        }
        g_tabc[bh * 1152 + t * 128 + w] = pc;
        g_tabg[bh * 1152 + t * 128 + w] = g4;
    }
}

// ---------------------------------------------------------------------------
// K2-fused: psff conv (bf16-split tensor-core implicit GEMM) + deformable
// sampling reduction. R11 structure, but A and B hi/lo interleaved as uint2:
// A fragments = 8 LDS.64 per tap (was 16 LDS.32); B fragments = 18 LDG.64
// per tap (was 36 LDG.32) -> ~half the L1 wavefronts, fewer issue slots,
// NO extra staging instructions or syncs (the R12 mistake).
// Grid: (8 oc-tiles of 72, 512 bh rows). 128 threads, warp tile 32px x 72oc.
// ---------------------------------------------------------------------------
#define SA_RSTRIDE 132                // uint2 per (r,icp) row
#define SP_STRIDE 132

__global__ __launch_bounds__(128, 4) void conv_fused_kernel(
        const float* __restrict__ in,
        const float* __restrict__ bias,
        const float* __restrict__ x,
        float* __restrict__ out) {
    const int oc0 = blockIdx.x * 72;
    const int bh = blockIdx.y;
    const int b = bh >> 7;
    const int h = bh & 127;
    const int tid = threadIdx.x;
    const int warp = tid >> 5;                // 0..3
    const int lane = tid & 31;
    const int g = lane >> 2;                  // 0..7
    const int t = lane & 3;                   // 0..3
    const int px0 = warp * 32;

    // buffer sized for max(sA2 = 24*132 uint2 = 25.3KB, sP = 72*132 f32 = 38KB)
    __shared__ __align__(16) uint32_t sBuf[9504];
    uint2* sA2 = (uint2*)sBuf;
    float* sP = (float*)sBuf;

    float acc[2][9][4];
#pragma unroll
    for (int mt = 0; mt < 2; mt++)
#pragma unroll
        for (int nt = 0; nt < 9; nt++)
#pragma unroll
            for (int q = 0; q < 4; q++) acc[mt][nt][q] = 0.f;

    const float* inb = in + b * C_ * HW;

    for (int chunk = 0; chunk < 4; chunk++) {
        __syncthreads();
        // stage A: 8 ic-pairs x 3 rows x 130 cols, hi/lo interleaved uint2
        for (int idx = tid; idx < 8 * 3 * 130; idx += 128) {
            int icp = idx / 390;
            int rem = idx - icp * 390;
            int r = rem / 130;
            int cc = rem - r * 130;
            int gh = h + r - 1;
            int gw = cc - 1;
            float v0 = 0.f, v1 = 0.f;
            if ((unsigned)gh < 128u && (unsigned)gw < 128u) {
                const float* p = inb + (chunk * 16 + 2 * icp) * HW + gh * 128 + gw;
                v0 = p[0];
                v1 = p[HW];
            }
            __nv_bfloat16 h0 = __float2bfloat16(v0);
            __nv_bfloat16 h1 = __float2bfloat16(v1);
            __nv_bfloat16 l0 = __float2bfloat16(v0 - __bfloat162float(h0));
            __nv_bfloat16 l1 = __float2bfloat16(v1 - __bfloat162float(h1));
            sA2[(r * 8 + icp) * SA_RSTRIDE + cc] =
                make_uint2(pack_bf16(h0, h1), pack_bf16(l0, l1));
        }
        __syncthreads();

#pragma unroll
        for (int s = 0; s < 9; s++) {
            const int r = s / 3;
            const int dw = s - 3 * r;

            // A fragments for 2 m-tiles, hi + lo (4 LDS.64 each, conflict-free)
            uint32_t ah[2][4], al[2][4];
#pragma unroll
            for (int mt = 0; mt < 2; mt++) {
                int cb = px0 + mt * 16 + g + dw;
                int base_lo = (r * 8 + t) * SA_RSTRIDE + cb;
                int base_hi = (r * 8 + t + 4) * SA_RSTRIDE + cb;
                uint2 q0 = sA2[base_lo];
                uint2 q1 = sA2[base_lo + 8];
                uint2 q2 = sA2[base_hi];
                uint2 q3 = sA2[base_hi + 8];
                ah[mt][0] = q0.x; al[mt][0] = q0.y;
                ah[mt][1] = q1.x; al[mt][1] = q1.y;
                ah[mt][2] = q2.x; al[mt][2] = q2.y;
                ah[mt][3] = q3.x; al[mt][3] = q3.y;
            }

            const int wbase = (s * 32 + chunk * 8 + t) * OCF + oc0 + g;
            // n-tiles in groups of 3; B = 2 LDG.64 per n-tile (hi/lo packed)
#pragma unroll
            for (int ntg = 0; ntg < 3; ntg++) {
                uint2 pb0[3], pb1[3];
#pragma unroll
                for (int u = 0; u < 3; u++) {
                    int widx = wbase + (ntg * 3 + u) * 8;
                    pb0[u] = g_w2[widx];
                    pb1[u] = g_w2[widx + 4 * OCF];
                }
#pragma unroll
                for (int u = 0; u < 3; u++) {
#pragma unroll
                    for (int mt = 0; mt < 2; mt++) {
                        float* a = acc[mt][ntg * 3 + u];
                        mma_bf16(a, ah[mt][0], ah[mt][1], ah[mt][2], ah[mt][3], pb0[u].x, pb1[u].x);
                        mma_bf16(a, ah[mt][0], ah[mt][1], ah[mt][2], ah[mt][3], pb0[u].y, pb1[u].y);
                        mma_bf16(a, al[mt][0], al[mt][1], al[mt][2], al[mt][3], pb0[u].x, pb1[u].x);
                    }
                }
            }
        }
    }

    // ---- epilogue phase 1: accumulators (+bias) -> sP[oc_local][px] ----
    __syncthreads();
#pragma unroll
    for (int nt = 0; nt < 9; nt++) {
        int oc_l = nt * 8 + 2 * t;
        float bva = __ldg(&bias[oc0 + oc_l]);
        float bvb = __ldg(&bias[oc0 + oc_l + 1]);
#pragma unroll
        for (int mt = 0; mt < 2; mt++) {
            int px = px0 + mt * 16 + g;
            sP[oc_l * SP_STRIDE + px]           = acc[mt][nt][0] + bva;
            sP[(oc_l + 1) * SP_STRIDE + px]     = acc[mt][nt][1] + bvb;
            sP[oc_l * SP_STRIDE + px + 8]       = acc[mt][nt][2] + bva;
            sP[(oc_l + 1) * SP_STRIDE + px + 8] = acc[mt][nt][3] + bvb;
        }
    }
    __syncthreads();

    // ---- epilogue phase 2: sampling reduction, 8 channels per thread ----
    const int w = tid;                         // 0..127
    const int c0 = blockIdx.x << 3;            // global channel base
    const float* xb = x + (size_t)(b * C_ + c0) * HW;

    float val[8] = {0.f, 0.f, 0.f, 0.f, 0.f, 0.f, 0.f, 0.f};

#pragma unroll
    for (int tt = 0; tt < 9; tt++) {
        uint32_t pc = g_tabc[bh * 1152 + tt * 128 + w];
        float4 g4 = g_tabg[bh * 1152 + tt * 128 + w];
        int ax = (int)(pc & 255u) - 1;
        int ay = (int)((pc >> 8) & 255u) - 1;
        int bx = (int)((pc >> 16) & 255u) - 1;
        int by = (int)(pc >> 24) - 1;
        bool vax = (unsigned)ax < 128u, vay = (unsigned)ay < 128u;
        bool vbx = (unsigned)bx < 128u, vby = (unsigned)by < 128u;
        int id0 = ax * 128 + ay;   // lt
        int id1 = bx * 128 + by;   // rb
        int id2 = ax * 128 + by;   // lb
        int id3 = bx * 128 + ay;   // rt
        const float* ps = &sP[tt * SP_STRIDE + w];
#pragma unroll
        for (int c = 0; c < 8; c++) {
            const float* xpl = xb + (size_t)c * HW;
            float s = 0.f;
            if (vax && vay) s += g4.x * __ldg(xpl + id0);
            if (vbx && vby) s += g4.y * __ldg(xpl + id1);
            if (vax && vby) s += g4.z * __ldg(xpl + id2);
            if (vbx && vay) s += g4.w * __ldg(xpl + id3);
            val[c] += s * ps[c * 9 * SP_STRIDE];
        }
    }

    float* ob = out + (size_t)(b * C_ + c0) * HW + h * 128 + w;
#pragma unroll
    for (int c = 0; c < 8; c++)
        ob[(size_t)c * HW] = val[c];
}

// ---------------------------------------------------------------------------
extern "C" void kernel_launch(void* const* d_in, const int* in_sizes, int n_in,
                              void* d_out, int out_size) {
    const float* feature_size    = (const float*)d_in[0];
    const float* feature_context = (const float*)d_in[1];
    const float* x               = (const float*)d_in[2];
    const float* p_conv_w        = (const float*)d_in[3];
    const float* p_conv_b        = (const float*)d_in[4];
    const float* f_conv_w        = (const float*)d_in[5];
    const float* f_conv_b        = (const float*)d_in[6];
    const float* m_conv_w        = (const float*)d_in[7];
    const float* m_conv_b        = (const float*)d_in[8];
    float* out = (float*)d_out;

    // K0: split/pack f_conv_w to interleaved bf16 hi/lo
    weight_split_kernel<<<(9 * 32 * OCF + 255) / 256, 256>>>(f_conv_w);

    // K1: merged offset(18) + mask(9, sigmoid) conv
    conv_small_merged_kernel<<<B_ * H_, 128>>>(feature_size, p_conv_w, p_conv_b,
                                               m_conv_w, m_conv_b);

    // K_samp: sampling tables from g_off/g_m
    samp_table_kernel<<<B_ * H_, 256>>>();

    // K2-fused: psff conv + sampling reduction -> out
    dim3 grid2(8, B_ * H_);
    conv_fused_kernel<<<grid2, 128>>>(feature_context, f_conv_b, x, out);
}

// round 14
// speedup vs baseline: 1.4726x; 1.3838x over previous
#include <cuda_runtime.h>
#include <cuda_fp16.h>
#include <math.h>
#include <stdint.h>

// Shapes (fixed by setup_inputs)
#define B_  4
#define C_  64
#define H_  128
#define W_  128
#define HW  (H_*W_)          // 16384
#define OCF 576              // f_conv output channels = C*9
#define KTOT 576             // 64*9 reduction size

// Scratch (__device__ globals: allocation-free rule)
__device__ float g_off[B_ * 18 * HW];
__device__ float g_m[B_ * 9 * HW];
// fp16 weights (hi only): [ (s*32 + icpair) * 576 + oc ], ic-pair packed in .b32
__device__ uint32_t g_wh[9 * 32 * OCF];
// sampling tables: per (bh, t, w): packed coords (u8, +1 bias) + 4 weights*m
__device__ uint32_t g_tabc[512 * 9 * 128];
__device__ float4   g_tabg[512 * 9 * 128];

__device__ __forceinline__ uint32_t pack_f16(__half lo, __half hi) {
    uint32_t l = (uint32_t)__half_as_ushort(lo);
    uint32_t h = (uint32_t)__half_as_ushort(hi);
    return l | (h << 16);
}

__device__ __forceinline__ void mma_f16(float* c,
        uint32_t a0, uint32_t a1, uint32_t a2, uint32_t a3,
        uint32_t b0, uint32_t b1) {
    asm volatile(
        "mma.sync.aligned.m16n8k16.row.col.f32.f16.f16.f32 "
        "{%0,%1,%2,%3}, {%4,%5,%6,%7}, {%8,%9}, {%0,%1,%2,%3};"
        : "+f"(c[0]), "+f"(c[1]), "+f"(c[2]), "+f"(c[3])
        : "r"(a0), "r"(a1), "r"(a2), "r"(a3), "r"(b0), "r"(b1));
}

// ---------------------------------------------------------------------------
// K0: quantize f_conv_w to fp16, ic-pair packed, k = tap*64 + ic.
// ---------------------------------------------------------------------------
__global__ void weight_split_kernel(const float* __restrict__ wgt) {
    int idx = blockIdx.x * blockDim.x + threadIdx.x;   // over 9*32*576
    if (idx >= 9 * 32 * OCF) return;
    int oc = idx % OCF;
    int tmp = idx / OCF;
    int icp = tmp & 31;
    int s = tmp >> 5;
    float w0 = wgt[oc * KTOT + (2 * icp) * 9 + s];
    float w1 = wgt[oc * KTOT + (2 * icp + 1) * 9 + s];
    g_wh[idx] = pack_f16(__float2half(w0), __float2half(w1));
}

// ---------------------------------------------------------------------------
// K1: merged small conv3x3: 27 outputs = 18 offset channels + 9 mask (sigmoid).
// ---------------------------------------------------------------------------
#define OCM  27
#define OCMP 28
__global__ void conv_small_merged_kernel(const float* __restrict__ in,
                                         const float* __restrict__ p_w,
                                         const float* __restrict__ p_b,
                                         const float* __restrict__ m_w,
                                         const float* __restrict__ m_b) {
    const int bh = blockIdx.x;
    const int b = bh >> 7;
    const int h = bh & 127;
    const int tid = threadIdx.x;      // 128 threads, tid == w
    const int w = tid;

    __shared__ __align__(16) float sIn[16 * 3 * 132];
    __shared__ __align__(16) float sW[144 * OCMP];

    float acc[OCMP];
#pragma unroll
    for (int i = 0; i < OCMP; i++) acc[i] = 0.f;

    const float* inb = in + b * C_ * HW;

    for (int chunk = 0; chunk < 4; chunk++) {
        for (int idx = tid; idx < 144 * OCMP; idx += 128) sW[idx] = 0.f;
        __syncthreads();
        for (int idx = tid; idx < 16 * 3 * 130; idx += 128) {
            int ic = idx / 390;
            int rem = idx - ic * 390;
            int r = rem / 130;
            int cc = rem - r * 130;
            int gh = h + r - 1;
            int gw = cc - 1;
            float v = 0.f;
            if ((unsigned)gh < 128u && (unsigned)gw < 128u)
                v = inb[(chunk * 16 + ic) * HW + gh * 128 + gw];
            sIn[(ic * 3 + r) * 132 + cc] = v;
        }
        for (int idx = tid; idx < 144 * OCM; idx += 128) {
            int oc = idx / 144;
            int k = idx - oc * 144;
            float wv = (oc < 18) ? p_w[oc * KTOT + chunk * 144 + k]
                                 : m_w[(oc - 18) * KTOT + chunk * 144 + k];
            sW[k * OCMP + oc] = wv;
        }
        __syncthreads();

#pragma unroll 4
        for (int ic = 0; ic < 16; ic++) {
#pragma unroll
            for (int r = 0; r < 3; r++) {
                float v0 = sIn[(ic * 3 + r) * 132 + w];
                float v1 = sIn[(ic * 3 + r) * 132 + w + 1];
                float v2 = sIn[(ic * 3 + r) * 132 + w + 2];
#pragma unroll
                for (int dw = 0; dw < 3; dw++) {
                    float v = (dw == 0) ? v0 : ((dw == 1) ? v1 : v2);
                    const float4* wp = (const float4*)&sW[(ic * 9 + r * 3 + dw) * OCMP];
#pragma unroll
                    for (int o4 = 0; o4 < OCMP / 4; o4++) {
                        float4 wv = wp[o4];
                        acc[o4 * 4 + 0] += v * wv.x;
                        acc[o4 * 4 + 1] += v * wv.y;
                        acc[o4 * 4 + 2] += v * wv.z;
                        acc[o4 * 4 + 3] += v * wv.w;
                    }
                }
            }
        }
        __syncthreads();
    }

#pragma unroll
    for (int oc = 0; oc < 18; oc++)
        g_off[((b * 18 + oc) * 128 + h) * 128 + w] = acc[oc] + p_b[oc];
#pragma unroll
    for (int oc = 0; oc < 9; oc++) {
        float v = acc[18 + oc] + m_b[oc];
        g_m[((b * 9 + oc) * 128 + h) * 128 + w] = 1.f / (1.f + expf(-v));
    }
}

// ---------------------------------------------------------------------------
// K_samp: per (b,h,w,t) sampling table.
// ---------------------------------------------------------------------------
__global__ __launch_bounds__(256) void samp_table_kernel() {
    const int bh = blockIdx.x;
    const int b = bh >> 7;
    const int h = bh & 127;
    const int tid = threadIdx.x;

    for (int item = tid; item < 9 * 128; item += 256) {
        int t = item >> 7;
        int w = item & 127;
        int i = t / 3, j = t - 3 * i;
        int hp = (i == 0) ? h - 1 : h;
        int ip = (i == 0) ? 2 : i - 1;
        int wp = (j == 0) ? w - 1 : w;
        int jp = (j == 0) ? 2 : j - 1;
        uint32_t pc = 0;
        float4 g4 = make_float4(0.f, 0.f, 0.f, 0.f);
        if (hp >= 0 && wp >= 0) {
            int k = ip * 3 + jp;
            float dxk = (float)(ip - 1);
            float dyk = (float)(jp - 1);
            int obase = ((b * 18 + k) * 128 + hp) * 128 + wp;
            float ox = g_off[obase];
            float oy = g_off[obase + 9 * HW];
            float px = (float)(hp + 1) + dxk + ox;
            float py = (float)(wp + 1) + dyk + oy;
            float fx = floorf(px), fy = floorf(py);
            float ltx = fminf(fmaxf(fx, 0.f), 129.f);
            float lty = fminf(fmaxf(fy, 0.f), 129.f);
            float rbx = fminf(fmaxf(fx + 1.f, 0.f), 129.f);
            float rby = fminf(fmaxf(fy + 1.f, 0.f), 129.f);
            float pxc = fminf(fmaxf(px, 0.f), 129.f);
            float pyc = fminf(fmaxf(py, 0.f), 129.f);
            float gxl = 1.f + (ltx - pxc);
            float gxr = 1.f - (rbx - pxc);
            float gyl = 1.f + (lty - pyc);
            float gyr = 1.f - (rby - pyc);
            float mv = g_m[((b * 9 + k) * 128 + hp) * 128 + wp];
            uint32_t axs = (uint32_t)(int)ltx;     // 0..129
            uint32_t ays = (uint32_t)(int)lty;
            uint32_t bxs = (uint32_t)(int)rbx;
            uint32_t bys = (uint32_t)(int)rby;
            pc = axs | (ays << 8) | (bxs << 16) | (bys << 24);
            g4 = make_float4(gxl * gyl * mv, gxr * gyr * mv,
                             gxl * gyr * mv, gxr * gyl * mv);
        }
        g_tabc[bh * 1152 + t * 128 + w] = pc;
        g_tabg[bh * 1152 + t * 128 + w] = g4;
    }
}

// ---------------------------------------------------------------------------
// K2-fused: psff conv as fp16 2-MMA-split tensor-core implicit GEMM +
// deformable sampling reduction. R11 structure exactly, but:
//   A = exact fp16 hi+lo split (a = ah + al, 22 mantissa bits)
//   B = fp16 hi only  ->  a*bh = ah*bh + al*bh : 2 MMAs per tile (was 3),
//       half the B fragment loads. Sole error = B fp16 quant ~1.2e-4.
// Grid: (8 oc-tiles of 72, 512 bh rows). 128 threads, warp tile 32px x 72oc.
// ---------------------------------------------------------------------------
#define ROW_STRIDE 136
#define ICP_STRIDE (3 * ROW_STRIDE)   // 408
#define SP_STRIDE 132

__global__ __launch_bounds__(128, 4) void conv_fused_kernel(
        const float* __restrict__ in,
        const float* __restrict__ bias,
        const float* __restrict__ x,
        float* __restrict__ out) {
    const int oc0 = blockIdx.x * 72;
    const int bh = blockIdx.y;
    const int b = bh >> 7;
    const int h = bh & 127;
    const int tid = threadIdx.x;
    const int warp = tid >> 5;                // 0..3
    const int lane = tid & 31;
    const int g = lane >> 2;                  // 0..7
    const int t = lane & 3;                   // 0..3
    const int px0 = warp * 32;

    // buffer sized for max(sAh+sAl = 6528 u32, sP = 72*132 f32 = 9504)
    __shared__ __align__(16) uint32_t sBuf[9504];
    uint32_t* sAh = sBuf;
    uint32_t* sAl = sBuf + 8 * ICP_STRIDE;
    float* sP = (float*)sBuf;

    float acc[2][9][4];
#pragma unroll
    for (int mt = 0; mt < 2; mt++)
#pragma unroll
        for (int nt = 0; nt < 9; nt++)
#pragma unroll
            for (int q = 0; q < 4; q++) acc[mt][nt][q] = 0.f;

    const float* inb = in + b * C_ * HW;

    for (int chunk = 0; chunk < 4; chunk++) {
        __syncthreads();
        // stage 16 ics as 8 ic-pairs, fp16 hi/lo, 3 rows x 130 padded cols
        for (int idx = tid; idx < 8 * 3 * 130; idx += 128) {
            int icp = idx / 390;
            int rem = idx - icp * 390;
            int r = rem / 130;
            int cc = rem - r * 130;
            int gh = h + r - 1;
            int gw = cc - 1;
            float v0 = 0.f, v1 = 0.f;
            if ((unsigned)gh < 128u && (unsigned)gw < 128u) {
                const float* p = inb + (chunk * 16 + 2 * icp) * HW + gh * 128 + gw;
                v0 = p[0];
                v1 = p[HW];
            }
            __half h0 = __float2half(v0);
            __half h1 = __float2half(v1);
            __half l0 = __float2half(v0 - __half2float(h0));
            __half l1 = __float2half(v1 - __half2float(h1));
            sAh[icp * ICP_STRIDE + r * ROW_STRIDE + cc] = pack_f16(h0, h1);
            sAl[icp * ICP_STRIDE + r * ROW_STRIDE + cc] = pack_f16(l0, l1);
        }
        __syncthreads();

#pragma unroll
        for (int s = 0; s < 9; s++) {
            const int r = s / 3;
            const int dw = s - 3 * r;

            // A fragments for 2 m-tiles, hi + lo
            uint32_t ah[2][4], al[2][4];
#pragma unroll
            for (int mt = 0; mt < 2; mt++) {
                int cb = px0 + mt * 16 + g + dw;
                int base_lo = t * ICP_STRIDE + r * ROW_STRIDE + cb;
                int base_hi = (t + 4) * ICP_STRIDE + r * ROW_STRIDE + cb;
                ah[mt][0] = sAh[base_lo];
                ah[mt][1] = sAh[base_lo + 8];
                ah[mt][2] = sAh[base_hi];
                ah[mt][3] = sAh[base_hi + 8];
                al[mt][0] = sAl[base_lo];
                al[mt][1] = sAl[base_lo + 8];
                al[mt][2] = sAl[base_hi];
                al[mt][3] = sAl[base_hi + 8];
            }

            const int wbase = (s * 32 + chunk * 8 + t) * OCF + oc0 + g;
            // n-tiles in groups of 3; B = hi only (2 LDG.32 per n-tile)
#pragma unroll
            for (int ntg = 0; ntg < 3; ntg++) {
                uint32_t bhr[3][2];
#pragma unroll
                for (int u = 0; u < 3; u++) {
                    int widx = wbase + (ntg * 3 + u) * 8;
                    bhr[u][0] = g_wh[widx];
                    bhr[u][1] = g_wh[widx + 4 * OCF];
                }
#pragma unroll
                for (int u = 0; u < 3; u++) {
#pragma unroll
                    for (int mt = 0; mt < 2; mt++) {
                        float* a = acc[mt][ntg * 3 + u];
                        mma_f16(a, ah[mt][0], ah[mt][1], ah[mt][2], ah[mt][3], bhr[u][0], bhr[u][1]);
                        mma_f16(a, al[mt][0], al[mt][1], al[mt][2], al[mt][3], bhr[u][0], bhr[u][1]);
                    }
                }
            }
        }
    }

    // ---- epilogue phase 1: accumulators (+bias) -> sP[oc_local][px] ----
    __syncthreads();
#pragma unroll
    for (int nt = 0; nt < 9; nt++) {
        int oc_l = nt * 8 + 2 * t;
        float bva = __ldg(&bias[oc0 + oc_l]);
        float bvb = __ldg(&bias[oc0 + oc_l + 1]);
#pragma unroll
        for (int mt = 0; mt < 2; mt++) {
            int px = px0 + mt * 16 + g;
            sP[oc_l * SP_STRIDE + px]           = acc[mt][nt][0] + bva;
            sP[(oc_l + 1) * SP_STRIDE + px]     = acc[mt][nt][1] + bvb;
            sP[oc_l * SP_STRIDE + px + 8]       = acc[mt][nt][2] + bva;
            sP[(oc_l + 1) * SP_STRIDE + px + 8] = acc[mt][nt][3] + bvb;
        }
    }
    __syncthreads();

    // ---- epilogue phase 2: sampling reduction, 8 channels per thread ----
    const int w = tid;                         // 0..127
    const int c0 = blockIdx.x << 3;            // global channel base
    const float* xb = x + (size_t)(b * C_ + c0) * HW;

    float val[8] = {0.f, 0.f, 0.f, 0.f, 0.f, 0.f, 0.f, 0.f};

#pragma unroll
    for (int tt = 0; tt < 9; tt++) {
        uint32_t pc = g_tabc[bh * 1152 + tt * 128 + w];
        float4 g4 = g_tabg[bh * 1152 + tt * 128 + w];
        int ax = (int)(pc & 255u) - 1;
        int ay = (int)((pc >> 8) & 255u) - 1;
        int bx = (int)((pc >> 16) & 255u) - 1;
        int by = (int)(pc >> 24) - 1;
        bool vax = (unsigned)ax < 128u, vay = (unsigned)ay < 128u;
        bool vbx = (unsigned)bx < 128u, vby = (unsigned)by < 128u;
        int id0 = ax * 128 + ay;   // lt
        int id1 = bx * 128 + by;   // rb
        int id2 = ax * 128 + by;   // lb
        int id3 = bx * 128 + ay;   // rt
        const float* ps = &sP[tt * SP_STRIDE + w];
#pragma unroll
        for (int c = 0; c < 8; c++) {
            const float* xpl = xb + (size_t)c * HW;
            float s = 0.f;
            if (vax && vay) s += g4.x * __ldg(xpl + id0);
            if (vbx && vby) s += g4.y * __ldg(xpl + id1);
            if (vax && vby) s += g4.z * __ldg(xpl + id2);
            if (vbx && vay) s += g4.w * __ldg(xpl + id3);
            val[c] += s * ps[c * 9 * SP_STRIDE];
        }
    }

    float* ob = out + (size_t)(b * C_ + c0) * HW + h * 128 + w;
#pragma unroll
    for (int c = 0; c < 8; c++)
        ob[(size_t)c * HW] = val[c];
}

// ---------------------------------------------------------------------------
extern "C" void kernel_launch(void* const* d_in, const int* in_sizes, int n_in,
                              void* d_out, int out_size) {
    const float* feature_size    = (const float*)d_in[0];
    const float* feature_context = (const float*)d_in[1];
    const float* x               = (const float*)d_in[2];
    const float* p_conv_w        = (const float*)d_in[3];
    const float* p_conv_b        = (const float*)d_in[4];
    const float* f_conv_w        = (const float*)d_in[5];
    const float* f_conv_b        = (const float*)d_in[6];
    const float* m_conv_w        = (const float*)d_in[7];
    const float* m_conv_b        = (const float*)d_in[8];
    float* out = (float*)d_out;

    // K0: quantize f_conv_w to fp16 pairs
    weight_split_kernel<<<(9 * 32 * OCF + 255) / 256, 256>>>(f_conv_w);

    // K1: merged offset(18) + mask(9, sigmoid) conv
    conv_small_merged_kernel<<<B_ * H_, 128>>>(feature_size, p_conv_w, p_conv_b,
                                               m_conv_w, m_conv_b);

    // K_samp: sampling tables from g_off/g_m
    samp_table_kernel<<<B_ * H_, 256>>>();

    // K2-fused: psff conv + sampling reduction -> out
    dim3 grid2(8, B_ * H_);
    conv_fused_kernel<<<grid2, 128>>>(feature_context, f_conv_b, x, out);
}

// round 15
// speedup vs baseline: 1.5464x; 1.0501x over previous
#include <cuda_runtime.h>
#include <cuda_fp16.h>
#include <math.h>
#include <stdint.h>

// Shapes (fixed by setup_inputs)
#define B_  4
#define C_  64
#define H_  128
#define W_  128
#define HW  (H_*W_)          // 16384
#define OCF 576              // f_conv output channels = C*9
#define KTOT 576             // 64*9 reduction size

// Scratch (__device__ globals: allocation-free rule)
__device__ float g_off[B_ * 18 * HW];
__device__ float g_m[B_ * 9 * HW];
// fp16 weights (hi only): [ (s*32 + icpair) * 576 + oc ], ic-pair packed in .b32
__device__ uint32_t g_wh[9 * 32 * OCF];
// sampling tables: per (bh, t, w): packed coords (u8, +1 bias) + 4 weights*m
__device__ uint32_t g_tabc[512 * 9 * 128];
__device__ float4   g_tabg[512 * 9 * 128];

__device__ __forceinline__ uint32_t pack_f16(__half lo, __half hi) {
    uint32_t l = (uint32_t)__half_as_ushort(lo);
    uint32_t h = (uint32_t)__half_as_ushort(hi);
    return l | (h << 16);
}

__device__ __forceinline__ void mma_f16(float* c,
        uint32_t a0, uint32_t a1, uint32_t a2, uint32_t a3,
        uint32_t b0, uint32_t b1) {
    asm volatile(
        "mma.sync.aligned.m16n8k16.row.col.f32.f16.f16.f32 "
        "{%0,%1,%2,%3}, {%4,%5,%6,%7}, {%8,%9}, {%0,%1,%2,%3};"
        : "+f"(c[0]), "+f"(c[1]), "+f"(c[2]), "+f"(c[3])
        : "r"(a0), "r"(a1), "r"(a2), "r"(a3), "r"(b0), "r"(b1));
}

// ---------------------------------------------------------------------------
// K0: quantize f_conv_w to fp16, ic-pair packed, k = tap*64 + ic.
// ---------------------------------------------------------------------------
__global__ void weight_split_kernel(const float* __restrict__ wgt) {
    int idx = blockIdx.x * blockDim.x + threadIdx.x;   // over 9*32*576
    if (idx >= 9 * 32 * OCF) return;
    int oc = idx % OCF;
    int tmp = idx / OCF;
    int icp = tmp & 31;
    int s = tmp >> 5;
    float w0 = wgt[oc * KTOT + (2 * icp) * 9 + s];
    float w1 = wgt[oc * KTOT + (2 * icp + 1) * 9 + s];
    g_wh[idx] = pack_f16(__float2half(w0), __float2half(w1));
}

// ---------------------------------------------------------------------------
// K1: merged small conv3x3: 27 outputs = 18 offset channels + 9 mask (sigmoid).
// ---------------------------------------------------------------------------
#define OCM  27
#define OCMP 28
__global__ void conv_small_merged_kernel(const float* __restrict__ in,
                                         const float* __restrict__ p_w,
                                         const float* __restrict__ p_b,
                                         const float* __restrict__ m_w,
                                         const float* __restrict__ m_b) {
    const int bh = blockIdx.x;
    const int b = bh >> 7;
    const int h = bh & 127;
    const int tid = threadIdx.x;      // 128 threads, tid == w
    const int w = tid;

    __shared__ __align__(16) float sIn[16 * 3 * 132];
    __shared__ __align__(16) float sW[144 * OCMP];

    float acc[OCMP];
#pragma unroll
    for (int i = 0; i < OCMP; i++) acc[i] = 0.f;

    const float* inb = in + b * C_ * HW;

    for (int chunk = 0; chunk < 4; chunk++) {
        for (int idx = tid; idx < 144 * OCMP; idx += 128) sW[idx] = 0.f;
        __syncthreads();
        for (int idx = tid; idx < 16 * 3 * 130; idx += 128) {
            int ic = idx / 390;
            int rem = idx - ic * 390;
            int r = rem / 130;
            int cc = rem - r * 130;
            int gh = h + r - 1;
            int gw = cc - 1;
            float v = 0.f;
            if ((unsigned)gh < 128u && (unsigned)gw < 128u)
                v = inb[(chunk * 16 + ic) * HW + gh * 128 + gw];
            sIn[(ic * 3 + r) * 132 + cc] = v;
        }
        for (int idx = tid; idx < 144 * OCM; idx += 128) {
            int oc = idx / 144;
            int k = idx - oc * 144;
            float wv = (oc < 18) ? p_w[oc * KTOT + chunk * 144 + k]
                                 : m_w[(oc - 18) * KTOT + chunk * 144 + k];
            sW[k * OCMP + oc] = wv;
        }
        __syncthreads();

#pragma unroll 4
        for (int ic = 0; ic < 16; ic++) {
#pragma unroll
            for (int r = 0; r < 3; r++) {
                float v0 = sIn[(ic * 3 + r) * 132 + w];
                float v1 = sIn[(ic * 3 + r) * 132 + w + 1];
                float v2 = sIn[(ic * 3 + r) * 132 + w + 2];
#pragma unroll
                for (int dw = 0; dw < 3; dw++) {
                    float v = (dw == 0) ? v0 : ((dw == 1) ? v1 : v2);
                    const float4* wp = (const float4*)&sW[(ic * 9 + r * 3 + dw) * OCMP];
#pragma unroll
                    for (int o4 = 0; o4 < OCMP / 4; o4++) {
                        float4 wv = wp[o4];
                        acc[o4 * 4 + 0] += v * wv.x;
                        acc[o4 * 4 + 1] += v * wv.y;
                        acc[o4 * 4 + 2] += v * wv.z;
                        acc[o4 * 4 + 3] += v * wv.w;
                    }
                }
            }
        }
        __syncthreads();
    }

#pragma unroll
    for (int oc = 0; oc < 18; oc++)
        g_off[((b * 18 + oc) * 128 + h) * 128 + w] = acc[oc] + p_b[oc];
#pragma unroll
    for (int oc = 0; oc < 9; oc++) {
        float v = acc[18 + oc] + m_b[oc];
        g_m[((b * 9 + oc) * 128 + h) * 128 + w] = 1.f / (1.f + expf(-v));
    }
}

// ---------------------------------------------------------------------------
// K_samp: per (b,h,w,t) sampling table.
// ---------------------------------------------------------------------------
__global__ __launch_bounds__(256) void samp_table_kernel() {
    const int bh = blockIdx.x;
    const int b = bh >> 7;
    const int h = bh & 127;
    const int tid = threadIdx.x;

    for (int item = tid; item < 9 * 128; item += 256) {
        int t = item >> 7;
        int w = item & 127;
        int i = t / 3, j = t - 3 * i;
        int hp = (i == 0) ? h - 1 : h;
        int ip = (i == 0) ? 2 : i - 1;
        int wp = (j == 0) ? w - 1 : w;
        int jp = (j == 0) ? 2 : j - 1;
        uint32_t pc = 0;
        float4 g4 = make_float4(0.f, 0.f, 0.f, 0.f);
        if (hp >= 0 && wp >= 0) {
            int k = ip * 3 + jp;
            float dxk = (float)(ip - 1);
            float dyk = (float)(jp - 1);
            int obase = ((b * 18 + k) * 128 + hp) * 128 + wp;
            float ox = g_off[obase];
            float oy = g_off[obase + 9 * HW];
            float px = (float)(hp + 1) + dxk + ox;
            float py = (float)(wp + 1) + dyk + oy;
            float fx = floorf(px), fy = floorf(py);
            float ltx = fminf(fmaxf(fx, 0.f), 129.f);
            float lty = fminf(fmaxf(fy, 0.f), 129.f);
            float rbx = fminf(fmaxf(fx + 1.f, 0.f), 129.f);
            float rby = fminf(fmaxf(fy + 1.f, 0.f), 129.f);
            float pxc = fminf(fmaxf(px, 0.f), 129.f);
            float pyc = fminf(fmaxf(py, 0.f), 129.f);
            float gxl = 1.f + (ltx - pxc);
            float gxr = 1.f - (rbx - pxc);
            float gyl = 1.f + (lty - pyc);
            float gyr = 1.f - (rby - pyc);
            float mv = g_m[((b * 9 + k) * 128 + hp) * 128 + wp];
            uint32_t axs = (uint32_t)(int)ltx;     // 0..129
            uint32_t ays = (uint32_t)(int)lty;
            uint32_t bxs = (uint32_t)(int)rbx;
            uint32_t bys = (uint32_t)(int)rby;
            pc = axs | (ays << 8) | (bxs << 16) | (bys << 24);
            g4 = make_float4(gxl * gyl * mv, gxr * gyr * mv,
                             gxl * gyr * mv, gxr * gyl * mv);
        }
        g_tabc[bh * 1152 + t * 128 + w] = pc;
        g_tabg[bh * 1152 + t * 128 + w] = g4;
    }
}

// ---------------------------------------------------------------------------
// K2-fused: psff conv as fp16 2-MMA-split tensor-core implicit GEMM +
// deformable sampling reduction.
// NEW vs R14: the whole chunk's B (72 rows x 72 u32 = 20.25KB) is staged in
// smem ONCE per chunk inside the existing A-sync window (no extra syncs, flat
// uint4 copy). sB row stride 72 (== 8 mod 32) makes fragment LDS pattern
// (s*8+t)*72 + nt*8 + g conflict-free. B L1 wavefronts drop ~4x (was 18
// scattered LDG.32 x 4 lines, identical across all 4 warps).
// Grid: (8 oc-tiles of 72, 512 bh rows). 128 threads, warp tile 32px x 72oc.
// ---------------------------------------------------------------------------
#define ROW_STRIDE 136
#define ICP_STRIDE (3 * ROW_STRIDE)   // 408
#define SB_STRIDE 72
#define SP_STRIDE 132

__global__ __launch_bounds__(128, 4) void conv_fused_kernel(
        const float* __restrict__ in,
        const float* __restrict__ bias,
        const float* __restrict__ x,
        float* __restrict__ out) {
    const int oc0 = blockIdx.x * 72;
    const int bh = blockIdx.y;
    const int b = bh >> 7;
    const int h = bh & 127;
    const int tid = threadIdx.x;
    const int warp = tid >> 5;                // 0..3
    const int lane = tid & 31;
    const int g = lane >> 2;                  // 0..7
    const int t = lane & 3;                   // 0..3
    const int px0 = warp * 32;

    // buffer: sAh+sAl (6528 u32) + sB (72*72 = 5184 u32) = 11712 u32 = 45.75KB
    // epilogue aliases sP (9504 u32) over the same buffer.
    __shared__ __align__(16) uint32_t sBuf[11712];
    uint32_t* sAh = sBuf;
    uint32_t* sAl = sBuf + 8 * ICP_STRIDE;
    uint32_t* sB  = sBuf + 16 * ICP_STRIDE;   // 6528
    float* sP = (float*)sBuf;

    float acc[2][9][4];
#pragma unroll
    for (int mt = 0; mt < 2; mt++)
#pragma unroll
        for (int nt = 0; nt < 9; nt++)
#pragma unroll
            for (int q = 0; q < 4; q++) acc[mt][nt][q] = 0.f;

    const float* inb = in + b * C_ * HW;

    for (int chunk = 0; chunk < 4; chunk++) {
        __syncthreads();
        // stage A: 16 ics as 8 ic-pairs, fp16 hi/lo, 3 rows x 130 padded cols
        for (int idx = tid; idx < 8 * 3 * 130; idx += 128) {
            int icp = idx / 390;
            int rem = idx - icp * 390;
            int r = rem / 130;
            int cc = rem - r * 130;
            int gh = h + r - 1;
            int gw = cc - 1;
            float v0 = 0.f, v1 = 0.f;
            if ((unsigned)gh < 128u && (unsigned)gw < 128u) {
                const float* p = inb + (chunk * 16 + 2 * icp) * HW + gh * 128 + gw;
                v0 = p[0];
                v1 = p[HW];
            }
            __half h0 = __float2half(v0);
            __half h1 = __float2half(v1);
            __half l0 = __float2half(v0 - __half2float(h0));
            __half l1 = __float2half(v1 - __half2float(h1));
            sAh[icp * ICP_STRIDE + r * ROW_STRIDE + cc] = pack_f16(h0, h1);
            sAl[icp * ICP_STRIDE + r * ROW_STRIDE + cc] = pack_f16(l0, l1);
        }
        // stage B: 72 rows (s*8 + icp) x 72 u32, vectorized uint4 copy
        for (int idx = tid; idx < 72 * 18; idx += 128) {
            int row = idx / 18;
            int q = idx - row * 18;
            int s = row >> 3;
            int icp = row & 7;
            const uint4* src = (const uint4*)(g_wh + (s * 32 + chunk * 8 + icp) * OCF + oc0);
            *(uint4*)(sB + row * SB_STRIDE + q * 4) = src[q];
        }
        __syncthreads();

#pragma unroll
        for (int s = 0; s < 9; s++) {
            const int r = s / 3;
            const int dw = s - 3 * r;

            // A fragments for 2 m-tiles, hi + lo
            uint32_t ah[2][4], al[2][4];
#pragma unroll
            for (int mt = 0; mt < 2; mt++) {
                int cb = px0 + mt * 16 + g + dw;
                int base_lo = t * ICP_STRIDE + r * ROW_STRIDE + cb;
                int base_hi = (t + 4) * ICP_STRIDE + r * ROW_STRIDE + cb;
                ah[mt][0] = sAh[base_lo];
                ah[mt][1] = sAh[base_lo + 8];
                ah[mt][2] = sAh[base_hi];
                ah[mt][3] = sAh[base_hi + 8];
                al[mt][0] = sAl[base_lo];
                al[mt][1] = sAl[base_lo + 8];
                al[mt][2] = sAl[base_hi];
                al[mt][3] = sAl[base_hi + 8];
            }

            const int rb0 = (s * 8 + t) * SB_STRIDE + g;
            const int rb1 = (s * 8 + t + 4) * SB_STRIDE + g;
            // n-tiles in groups of 3; B = 2 LDS.32 per n-tile, conflict-free
#pragma unroll
            for (int ntg = 0; ntg < 3; ntg++) {
                uint32_t bhr[3][2];
#pragma unroll
                for (int u = 0; u < 3; u++) {
                    int col = (ntg * 3 + u) * 8;
                    bhr[u][0] = sB[rb0 + col];
                    bhr[u][1] = sB[rb1 + col];
                }
#pragma unroll
                for (int u = 0; u < 3; u++) {
#pragma unroll
                    for (int mt = 0; mt < 2; mt++) {
                        float* a = acc[mt][ntg * 3 + u];
                        mma_f16(a, ah[mt][0], ah[mt][1], ah[mt][2], ah[mt][3], bhr[u][0], bhr[u][1]);
                        mma_f16(a, al[mt][0], al[mt][1], al[mt][2], al[mt][3], bhr[u][0], bhr[u][1]);
                    }
                }
            }
        }
    }

    // ---- epilogue phase 1: accumulators (+bias) -> sP[oc_local][px] ----
    __syncthreads();
#pragma unroll
    for (int nt = 0; nt < 9; nt++) {
        int oc_l = nt * 8 + 2 * t;
        float bva = __ldg(&bias[oc0 + oc_l]);
        float bvb = __ldg(&bias[oc0 + oc_l + 1]);
#pragma unroll
        for (int mt = 0; mt < 2; mt++) {
            int px = px0 + mt * 16 + g;
            sP[oc_l * SP_STRIDE + px]           = acc[mt][nt][0] + bva;
            sP[(oc_l + 1) * SP_STRIDE + px]     = acc[mt][nt][1] + bvb;
            sP[oc_l * SP_STRIDE + px + 8]       = acc[mt][nt][2] + bva;
            sP[(oc_l + 1) * SP_STRIDE + px + 8] = acc[mt][nt][3] + bvb;
        }
    }
    __syncthreads();

    // ---- epilogue phase 2: sampling reduction, 8 channels per thread ----
    const int w = tid;                         // 0..127
    const int c0 = blockIdx.x << 3;            // global channel base
    const float* xb = x + (size_t)(b * C_ + c0) * HW;

    float val[8] = {0.f, 0.f, 0.f, 0.f, 0.f, 0.f, 0.f, 0.f};

#pragma unroll
    for (int tt = 0; tt < 9; tt++) {
        uint32_t pc = g_tabc[bh * 1152 + tt * 128 + w];
        float4 g4 = g_tabg[bh * 1152 + tt * 128 + w];
        int ax = (int)(pc & 255u) - 1;
        int ay = (int)((pc >> 8) & 255u) - 1;
        int bx = (int)((pc >> 16) & 255u) - 1;
        int by = (int)(pc >> 24) - 1;
        bool vax = (unsigned)ax < 128u, vay = (unsigned)ay < 128u;
        bool vbx = (unsigned)bx < 128u, vby = (unsigned)by < 128u;
        int id0 = ax * 128 + ay;   // lt
        int id1 = bx * 128 + by;   // rb
        int id2 = ax * 128 + by;   // lb
        int id3 = bx * 128 + ay;   // rt
        const float* ps = &sP[tt * SP_STRIDE + w];
#pragma unroll
        for (int c = 0; c < 8; c++) {
            const float* xpl = xb + (size_t)c * HW;
            float s = 0.f;
            if (vax && vay) s += g4.x * __ldg(xpl + id0);
            if (vbx && vby) s += g4.y * __ldg(xpl + id1);
            if (vax && vby) s += g4.z * __ldg(xpl + id2);
            if (vbx && vay) s += g4.w * __ldg(xpl + id3);
            val[c] += s * ps[c * 9 * SP_STRIDE];
        }
    }

    float* ob = out + (size_t)(b * C_ + c0) * HW + h * 128 + w;
#pragma unroll
    for (int c = 0; c < 8; c++)
        ob[(size_t)c * HW] = val[c];
}

// ---------------------------------------------------------------------------
extern "C" void kernel_launch(void* const* d_in, const int* in_sizes, int n_in,
                              void* d_out, int out_size) {
    const float* feature_size    = (const float*)d_in[0];
    const float* feature_context = (const float*)d_in[1];
    const float* x               = (const float*)d_in[2];
    const float* p_conv_w        = (const float*)d_in[3];
    const float* p_conv_b        = (const float*)d_in[4];
    const float* f_conv_w        = (const float*)d_in[5];
    const float* f_conv_b        = (const float*)d_in[6];
    const float* m_conv_w        = (const float*)d_in[7];
    const float* m_conv_b        = (const float*)d_in[8];
    float* out = (float*)d_out;

    // K0: quantize f_conv_w to fp16 pairs
    weight_split_kernel<<<(9 * 32 * OCF + 255) / 256, 256>>>(f_conv_w);

    // K1: merged offset(18) + mask(9, sigmoid) conv
    conv_small_merged_kernel<<<B_ * H_, 128>>>(feature_size, p_conv_w, p_conv_b,
                                               m_conv_w, m_conv_b);

    // K_samp: sampling tables from g_off/g_m
    samp_table_kernel<<<B_ * H_, 256>>>();

    // K2-fused: psff conv + sampling reduction -> out
    dim3 grid2(8, B_ * H_);
    conv_fused_kernel<<<grid2, 128>>>(feature_context, f_conv_b, x, out);
}

// round 16
// speedup vs baseline: 1.8608x; 1.2033x over previous
#include <cuda_runtime.h>
#include <cuda_fp16.h>
#include <math.h>
#include <stdint.h>

// Shapes (fixed by setup_inputs)
#define B_  4
#define C_  64
#define H_  128
#define W_  128
#define HW  (H_*W_)          // 16384
#define OCF 576              // f_conv output channels = C*9
#define KTOT 576             // 64*9 reduction size

// Scratch (__device__ globals: allocation-free rule)
__device__ float g_off[B_ * 18 * HW];
__device__ float g_m[B_ * 9 * HW];
// fp16 weights (hi only): [ (s*32 + icpair) * 576 + oc ], ic-pair packed in .b32
__device__ uint32_t g_wh[9 * 32 * OCF];
// fp16 small weights (offset 18 + mask 9, padded to 32): [(s*32+icp)*32 + oc]
__device__ uint32_t g_w1[9 * 32 * 32];
// sampling tables: per (bh, t, w): packed coords (u8, +1 bias) + 4 weights*m
__device__ uint32_t g_tabc[512 * 9 * 128];
__device__ float4   g_tabg[512 * 9 * 128];

__device__ __forceinline__ uint32_t pack_f16(__half lo, __half hi) {
    uint32_t l = (uint32_t)__half_as_ushort(lo);
    uint32_t h = (uint32_t)__half_as_ushort(hi);
    return l | (h << 16);
}

__device__ __forceinline__ void mma_f16(float* c,
        uint32_t a0, uint32_t a1, uint32_t a2, uint32_t a3,
        uint32_t b0, uint32_t b1) {
    asm volatile(
        "mma.sync.aligned.m16n8k16.row.col.f32.f16.f16.f32 "
        "{%0,%1,%2,%3}, {%4,%5,%6,%7}, {%8,%9}, {%0,%1,%2,%3};"
        : "+f"(c[0]), "+f"(c[1]), "+f"(c[2]), "+f"(c[3])
        : "r"(a0), "r"(a1), "r"(a2), "r"(a3), "r"(b0), "r"(b1));
}

// ---------------------------------------------------------------------------
// K0a: quantize f_conv_w to fp16, ic-pair packed, k = tap*64 + ic.
// ---------------------------------------------------------------------------
__global__ void weight_split_kernel(const float* __restrict__ wgt) {
    int idx = blockIdx.x * blockDim.x + threadIdx.x;   // over 9*32*576
    if (idx >= 9 * 32 * OCF) return;
    int oc = idx % OCF;
    int tmp = idx / OCF;
    int icp = tmp & 31;
    int s = tmp >> 5;
    float w0 = wgt[oc * KTOT + (2 * icp) * 9 + s];
    float w1 = wgt[oc * KTOT + (2 * icp + 1) * 9 + s];
    g_wh[idx] = pack_f16(__float2half(w0), __float2half(w1));
}

// ---------------------------------------------------------------------------
// K0b: pack small conv weights (p_conv 18 oc + m_conv 9 oc, pad to 32).
// ---------------------------------------------------------------------------
__global__ void weight_split_small_kernel(const float* __restrict__ p_w,
                                          const float* __restrict__ m_w) {
    int idx = blockIdx.x * blockDim.x + threadIdx.x;   // over 9*32*32
    if (idx >= 9 * 32 * 32) return;
    int oc = idx & 31;
    int tmp = idx >> 5;
    int icp = tmp & 31;
    int s = tmp >> 5;
    float w0 = 0.f, w1 = 0.f;
    if (oc < 18) {
        w0 = p_w[oc * KTOT + (2 * icp) * 9 + s];
        w1 = p_w[oc * KTOT + (2 * icp + 1) * 9 + s];
    } else if (oc < 27) {
        w0 = m_w[(oc - 18) * KTOT + (2 * icp) * 9 + s];
        w1 = m_w[(oc - 18) * KTOT + (2 * icp + 1) * 9 + s];
    }
    g_w1[idx] = pack_f16(__float2half(w0), __float2half(w1));
}

#define ROW_STRIDE 136
#define ICP_STRIDE (3 * ROW_STRIDE)   // 408

// ---------------------------------------------------------------------------
// K1: offset(18) + mask(9, sigmoid) conv via fp16 2-MMA-split tensor cores.
// Grid 512 (bh rows), 128 threads, warp tile 32px x 32oc (27 used).
// Same A staging as the fused kernel; B tiny (9KB/chunk), stride 40 (==8 mod
// 32) -> conflict-free fragment LDS. Epilogue: direct scattered STG.
// ---------------------------------------------------------------------------
#define SB1_STRIDE 40

__global__ __launch_bounds__(128) void conv_small_mma_kernel(
        const float* __restrict__ in,
        const float* __restrict__ p_b,
        const float* __restrict__ m_b) {
    const int bh = blockIdx.x;
    const int b = bh >> 7;
    const int h = bh & 127;
    const int tid = threadIdx.x;
    const int warp = tid >> 5;                // 0..3
    const int lane = tid & 31;
    const int g = lane >> 2;                  // 0..7
    const int t = lane & 3;                   // 0..3
    const int px0 = warp * 32;

    __shared__ __align__(16) uint32_t sAh[8 * ICP_STRIDE];
    __shared__ __align__(16) uint32_t sAl[8 * ICP_STRIDE];
    __shared__ __align__(16) uint32_t sB[72 * SB1_STRIDE];

    float acc[2][4][4];
#pragma unroll
    for (int mt = 0; mt < 2; mt++)
#pragma unroll
        for (int nt = 0; nt < 4; nt++)
#pragma unroll
            for (int q = 0; q < 4; q++) acc[mt][nt][q] = 0.f;

    const float* inb = in + b * C_ * HW;

    for (int chunk = 0; chunk < 4; chunk++) {
        __syncthreads();
        // stage A: 16 ics as 8 ic-pairs, fp16 hi/lo, 3 rows x 130 padded cols
        for (int idx = tid; idx < 8 * 3 * 130; idx += 128) {
            int icp = idx / 390;
            int rem = idx - icp * 390;
            int r = rem / 130;
            int cc = rem - r * 130;
            int gh = h + r - 1;
            int gw = cc - 1;
            float v0 = 0.f, v1 = 0.f;
            if ((unsigned)gh < 128u && (unsigned)gw < 128u) {
                const float* p = inb + (chunk * 16 + 2 * icp) * HW + gh * 128 + gw;
                v0 = p[0];
                v1 = p[HW];
            }
            __half h0 = __float2half(v0);
            __half h1 = __float2half(v1);
            __half l0 = __float2half(v0 - __half2float(h0));
            __half l1 = __float2half(v1 - __half2float(h1));
            sAh[icp * ICP_STRIDE + r * ROW_STRIDE + cc] = pack_f16(h0, h1);
            sAl[icp * ICP_STRIDE + r * ROW_STRIDE + cc] = pack_f16(l0, l1);
        }
        // stage B: 72 rows x 32 u32, vectorized
        for (int idx = tid; idx < 72 * 8; idx += 128) {
            int row = idx >> 3;
            int q = idx & 7;
            int s = row >> 3;
            int icp = row & 7;
            const uint4* src = (const uint4*)(g_w1 + (s * 32 + chunk * 8 + icp) * 32);
            *(uint4*)(sB + row * SB1_STRIDE + q * 4) = src[q];
        }
        __syncthreads();

#pragma unroll
        for (int s = 0; s < 9; s++) {
            const int r = s / 3;
            const int dw = s - 3 * r;

            uint32_t ah[2][4], al[2][4];
#pragma unroll
            for (int mt = 0; mt < 2; mt++) {
                int cb = px0 + mt * 16 + g + dw;
                int base_lo = t * ICP_STRIDE + r * ROW_STRIDE + cb;
                int base_hi = (t + 4) * ICP_STRIDE + r * ROW_STRIDE + cb;
                ah[mt][0] = sAh[base_lo];
                ah[mt][1] = sAh[base_lo + 8];
                ah[mt][2] = sAh[base_hi];
                ah[mt][3] = sAh[base_hi + 8];
                al[mt][0] = sAl[base_lo];
                al[mt][1] = sAl[base_lo + 8];
                al[mt][2] = sAl[base_hi];
                al[mt][3] = sAl[base_hi + 8];
            }

            const int rb0 = (s * 8 + t) * SB1_STRIDE + g;
            const int rb1 = (s * 8 + t + 4) * SB1_STRIDE + g;
#pragma unroll
            for (int nt = 0; nt < 4; nt++) {
                uint32_t b0 = sB[rb0 + nt * 8];
                uint32_t b1 = sB[rb1 + nt * 8];
#pragma unroll
                for (int mt = 0; mt < 2; mt++) {
                    float* a = acc[mt][nt];
                    mma_f16(a, ah[mt][0], ah[mt][1], ah[mt][2], ah[mt][3], b0, b1);
                    mma_f16(a, al[mt][0], al[mt][1], al[mt][2], al[mt][3], b0, b1);
                }
            }
        }
    }

    // epilogue: direct scattered stores (27 live ocs)
#pragma unroll
    for (int nt = 0; nt < 4; nt++) {
#pragma unroll
        for (int q2 = 0; q2 < 2; q2++) {
            int oc = nt * 8 + 2 * t + q2;
            bool is_off = oc < 18;
            bool is_m = (oc >= 18) && (oc < 27);
            float bv = is_off ? __ldg(&p_b[oc]) : (is_m ? __ldg(&m_b[oc - 18]) : 0.f);
#pragma unroll
            for (int mt = 0; mt < 2; mt++) {
#pragma unroll
                for (int ph = 0; ph < 2; ph++) {
                    float v = acc[mt][nt][ph * 2 + q2] + bv;
                    int px = px0 + mt * 16 + g + ph * 8;
                    if (is_off)
                        g_off[((b * 18 + oc) * 128 + h) * 128 + px] = v;
                    else if (is_m)
                        g_m[((b * 9 + (oc - 18)) * 128 + h) * 128 + px] =
                            1.f / (1.f + expf(-v));
                }
            }
        }
    }
}

// ---------------------------------------------------------------------------
// K_samp: per (b,h,w,t) sampling table.
// ---------------------------------------------------------------------------
__global__ __launch_bounds__(256) void samp_table_kernel() {
    const int bh = blockIdx.x;
    const int b = bh >> 7;
    const int h = bh & 127;
    const int tid = threadIdx.x;

    for (int item = tid; item < 9 * 128; item += 256) {
        int t = item >> 7;
        int w = item & 127;
        int i = t / 3, j = t - 3 * i;
        int hp = (i == 0) ? h - 1 : h;
        int ip = (i == 0) ? 2 : i - 1;
        int wp = (j == 0) ? w - 1 : w;
        int jp = (j == 0) ? 2 : j - 1;
        uint32_t pc = 0;
        float4 g4 = make_float4(0.f, 0.f, 0.f, 0.f);
        if (hp >= 0 && wp >= 0) {
            int k = ip * 3 + jp;
            float dxk = (float)(ip - 1);
            float dyk = (float)(jp - 1);
            int obase = ((b * 18 + k) * 128 + hp) * 128 + wp;
            float ox = g_off[obase];
            float oy = g_off[obase + 9 * HW];
            float px = (float)(hp + 1) + dxk + ox;
            float py = (float)(wp + 1) + dyk + oy;
            float fx = floorf(px), fy = floorf(py);
            float ltx = fminf(fmaxf(fx, 0.f), 129.f);
            float lty = fminf(fmaxf(fy, 0.f), 129.f);
            float rbx = fminf(fmaxf(fx + 1.f, 0.f), 129.f);
            float rby = fminf(fmaxf(fy + 1.f, 0.f), 129.f);
            float pxc = fminf(fmaxf(px, 0.f), 129.f);
            float pyc = fminf(fmaxf(py, 0.f), 129.f);
            float gxl = 1.f + (ltx - pxc);
            float gxr = 1.f - (rbx - pxc);
            float gyl = 1.f + (lty - pyc);
            float gyr = 1.f - (rby - pyc);
            float mv = g_m[((b * 9 + k) * 128 + hp) * 128 + wp];
            uint32_t axs = (uint32_t)(int)ltx;     // 0..129
            uint32_t ays = (uint32_t)(int)lty;
            uint32_t bxs = (uint32_t)(int)rbx;
            uint32_t bys = (uint32_t)(int)rby;
            pc = axs | (ays << 8) | (bxs << 16) | (bys << 24);
            g4 = make_float4(gxl * gyl * mv, gxr * gyr * mv,
                             gxl * gyr * mv, gxr * gyl * mv);
        }
        g_tabc[bh * 1152 + t * 128 + w] = pc;
        g_tabg[bh * 1152 + t * 128 + w] = g4;
    }
}

// ---------------------------------------------------------------------------
// K2-fused: psff conv as fp16 2-MMA-split tensor-core implicit GEMM +
// deformable sampling reduction. (R15 winner, unchanged.)
// ---------------------------------------------------------------------------
#define SB_STRIDE 72
#define SP_STRIDE 132

__global__ __launch_bounds__(128, 4) void conv_fused_kernel(
        const float* __restrict__ in,
        const float* __restrict__ bias,
        const float* __restrict__ x,
        float* __restrict__ out) {
    const int oc0 = blockIdx.x * 72;
    const int bh = blockIdx.y;
    const int b = bh >> 7;
    const int h = bh & 127;
    const int tid = threadIdx.x;
    const int warp = tid >> 5;                // 0..3
    const int lane = tid & 31;
    const int g = lane >> 2;                  // 0..7
    const int t = lane & 3;                   // 0..3
    const int px0 = warp * 32;

    __shared__ __align__(16) uint32_t sBuf[11712];
    uint32_t* sAh = sBuf;
    uint32_t* sAl = sBuf + 8 * ICP_STRIDE;
    uint32_t* sB  = sBuf + 16 * ICP_STRIDE;   // 6528
    float* sP = (float*)sBuf;

    float acc[2][9][4];
#pragma unroll
    for (int mt = 0; mt < 2; mt++)
#pragma unroll
        for (int nt = 0; nt < 9; nt++)
#pragma unroll
            for (int q = 0; q < 4; q++) acc[mt][nt][q] = 0.f;

    const float* inb = in + b * C_ * HW;

    for (int chunk = 0; chunk < 4; chunk++) {
        __syncthreads();
        // stage A: 16 ics as 8 ic-pairs, fp16 hi/lo, 3 rows x 130 padded cols
        for (int idx = tid; idx < 8 * 3 * 130; idx += 128) {
            int icp = idx / 390;
            int rem = idx - icp * 390;
            int r = rem / 130;
            int cc = rem - r * 130;
            int gh = h + r - 1;
            int gw = cc - 1;
            float v0 = 0.f, v1 = 0.f;
            if ((unsigned)gh < 128u && (unsigned)gw < 128u) {
                const float* p = inb + (chunk * 16 + 2 * icp) * HW + gh * 128 + gw;
                v0 = p[0];
                v1 = p[HW];
            }
            __half h0 = __float2half(v0);
            __half h1 = __float2half(v1);
            __half l0 = __float2half(v0 - __half2float(h0));
            __half l1 = __float2half(v1 - __half2float(h1));
            sAh[icp * ICP_STRIDE + r * ROW_STRIDE + cc] = pack_f16(h0, h1);
            sAl[icp * ICP_STRIDE + r * ROW_STRIDE + cc] = pack_f16(l0, l1);
        }
        // stage B: 72 rows (s*8 + icp) x 72 u32, vectorized uint4 copy
        for (int idx = tid; idx < 72 * 18; idx += 128) {
            int row = idx / 18;
            int q = idx - row * 18;
            int s = row >> 3;
            int icp = row & 7;
            const uint4* src = (const uint4*)(g_wh + (s * 32 + chunk * 8 + icp) * OCF + oc0);
            *(uint4*)(sB + row * SB_STRIDE + q * 4) = src[q];
        }
        __syncthreads();

#pragma unroll
        for (int s = 0; s < 9; s++) {
            const int r = s / 3;
            const int dw = s - 3 * r;

            uint32_t ah[2][4], al[2][4];
#pragma unroll
            for (int mt = 0; mt < 2; mt++) {
                int cb = px0 + mt * 16 + g + dw;
                int base_lo = t * ICP_STRIDE + r * ROW_STRIDE + cb;
                int base_hi = (t + 4) * ICP_STRIDE + r * ROW_STRIDE + cb;
                ah[mt][0] = sAh[base_lo];
                ah[mt][1] = sAh[base_lo + 8];
                ah[mt][2] = sAh[base_hi];
                ah[mt][3] = sAh[base_hi + 8];
                al[mt][0] = sAl[base_lo];
                al[mt][1] = sAl[base_lo + 8];
                al[mt][2] = sAl[base_hi];
                al[mt][3] = sAl[base_hi + 8];
            }

            const int rb0 = (s * 8 + t) * SB_STRIDE + g;
            const int rb1 = (s * 8 + t + 4) * SB_STRIDE + g;
#pragma unroll
            for (int ntg = 0; ntg < 3; ntg++) {
                uint32_t bhr[3][2];
#pragma unroll
                for (int u = 0; u < 3; u++) {
                    int col = (ntg * 3 + u) * 8;
                    bhr[u][0] = sB[rb0 + col];
                    bhr[u][1] = sB[rb1 + col];
                }
#pragma unroll
                for (int u = 0; u < 3; u++) {
#pragma unroll
                    for (int mt = 0; mt < 2; mt++) {
                        float* a = acc[mt][ntg * 3 + u];
                        mma_f16(a, ah[mt][0], ah[mt][1], ah[mt][2], ah[mt][3], bhr[u][0], bhr[u][1]);
                        mma_f16(a, al[mt][0], al[mt][1], al[mt][2], al[mt][3], bhr[u][0], bhr[u][1]);
                    }
                }
            }
        }
    }

    // ---- epilogue phase 1: accumulators (+bias) -> sP[oc_local][px] ----
    __syncthreads();
#pragma unroll
    for (int nt = 0; nt < 9; nt++) {
        int oc_l = nt * 8 + 2 * t;
        float bva = __ldg(&bias[oc0 + oc_l]);
        float bvb = __ldg(&bias[oc0 + oc_l + 1]);
#pragma unroll
        for (int mt = 0; mt < 2; mt++) {
            int px = px0 + mt * 16 + g;
            sP[oc_l * SP_STRIDE + px]           = acc[mt][nt][0] + bva;
            sP[(oc_l + 1) * SP_STRIDE + px]     = acc[mt][nt][1] + bvb;
            sP[oc_l * SP_STRIDE + px + 8]       = acc[mt][nt][2] + bva;
            sP[(oc_l + 1) * SP_STRIDE + px + 8] = acc[mt][nt][3] + bvb;
        }
    }
    __syncthreads();

    // ---- epilogue phase 2: sampling reduction, 8 channels per thread ----
    const int w = tid;                         // 0..127
    const int c0 = blockIdx.x << 3;            // global channel base
    const float* xb = x + (size_t)(b * C_ + c0) * HW;

    float val[8] = {0.f, 0.f, 0.f, 0.f, 0.f, 0.f, 0.f, 0.f};

#pragma unroll
    for (int tt = 0; tt < 9; tt++) {
        uint32_t pc = g_tabc[bh * 1152 + tt * 128 + w];
        float4 g4 = g_tabg[bh * 1152 + tt * 128 + w];
        int ax = (int)(pc & 255u) - 1;
        int ay = (int)((pc >> 8) & 255u) - 1;
        int bx = (int)((pc >> 16) & 255u) - 1;
        int by = (int)(pc >> 24) - 1;
        bool vax = (unsigned)ax < 128u, vay = (unsigned)ay < 128u;
        bool vbx = (unsigned)bx < 128u, vby = (unsigned)by < 128u;
        int id0 = ax * 128 + ay;   // lt
        int id1 = bx * 128 + by;   // rb
        int id2 = ax * 128 + by;   // lb
        int id3 = bx * 128 + ay;   // rt
        const float* ps = &sP[tt * SP_STRIDE + w];
#pragma unroll
        for (int c = 0; c < 8; c++) {
            const float* xpl = xb + (size_t)c * HW;
            float s = 0.f;
            if (vax && vay) s += g4.x * __ldg(xpl + id0);
            if (vbx && vby) s += g4.y * __ldg(xpl + id1);
            if (vax && vby) s += g4.z * __ldg(xpl + id2);
            if (vbx && vay) s += g4.w * __ldg(xpl + id3);
            val[c] += s * ps[c * 9 * SP_STRIDE];
        }
    }

    float* ob = out + (size_t)(b * C_ + c0) * HW + h * 128 + w;
#pragma unroll
    for (int c = 0; c < 8; c++)
        ob[(size_t)c * HW] = val[c];
}

// ---------------------------------------------------------------------------
extern "C" void kernel_launch(void* const* d_in, const int* in_sizes, int n_in,
                              void* d_out, int out_size) {
    const float* feature_size    = (const float*)d_in[0];
    const float* feature_context = (const float*)d_in[1];
    const float* x               = (const float*)d_in[2];
    const float* p_conv_w        = (const float*)d_in[3];
    const float* p_conv_b        = (const float*)d_in[4];
    const float* f_conv_w        = (const float*)d_in[5];
    const float* f_conv_b        = (const float*)d_in[6];
    const float* m_conv_w        = (const float*)d_in[7];
    const float* m_conv_b        = (const float*)d_in[8];
    float* out = (float*)d_out;

    // K0: quantize weights to fp16
    weight_split_kernel<<<(9 * 32 * OCF + 255) / 256, 256>>>(f_conv_w);
    weight_split_small_kernel<<<(9 * 32 * 32 + 255) / 256, 256>>>(p_conv_w, m_conv_w);

    // K1: offset(18) + mask(9, sigmoid) conv via tensor cores
    conv_small_mma_kernel<<<B_ * H_, 128>>>(feature_size, p_conv_b, m_conv_b);

    // K_samp: sampling tables from g_off/g_m
    samp_table_kernel<<<B_ * H_, 256>>>();

    // K2-fused: psff conv + sampling reduction -> out
    dim3 grid2(8, B_ * H_);
    conv_fused_kernel<<<grid2, 128>>>(feature_context, f_conv_b, x, out);
}

// round 17
// speedup vs baseline: 2.3025x; 1.2374x over previous
#include <cuda_runtime.h>
#include <cuda_fp16.h>
#include <math.h>
#include <stdint.h>

// Shapes (fixed by setup_inputs)
#define B_  4
#define C_  64
#define H_  128
#define W_  128
#define HW  (H_*W_)          // 16384
#define OCF 576              // f_conv output channels = C*9
#define KTOT 576             // 64*9 reduction size

// Scratch (__device__ globals: allocation-free rule)
__device__ float g_off[B_ * 18 * HW];
__device__ float g_m[B_ * 9 * HW];
// fp16 weights: [ (s*32 + icpair) * 576 + oc ], ic-pair packed in .b32
__device__ uint32_t g_wh[9 * 32 * OCF];
// fp16 small weights (offset 18 + mask 9, padded to 32): [(s*32+icp)*32 + oc]
__device__ uint32_t g_w1[9 * 32 * 32];
// sampling tables: per (bh, t, w): packed coords (u8, +1 bias) + 4 weights*m
__device__ uint32_t g_tabc[512 * 9 * 128];
__device__ float4   g_tabg[512 * 9 * 128];

__device__ __forceinline__ uint32_t pack_f16(__half lo, __half hi) {
    uint32_t l = (uint32_t)__half_as_ushort(lo);
    uint32_t h = (uint32_t)__half_as_ushort(hi);
    return l | (h << 16);
}

__device__ __forceinline__ void mma_f16(float* c,
        uint32_t a0, uint32_t a1, uint32_t a2, uint32_t a3,
        uint32_t b0, uint32_t b1) {
    asm volatile(
        "mma.sync.aligned.m16n8k16.row.col.f32.f16.f16.f32 "
        "{%0,%1,%2,%3}, {%4,%5,%6,%7}, {%8,%9}, {%0,%1,%2,%3};"
        : "+f"(c[0]), "+f"(c[1]), "+f"(c[2]), "+f"(c[3])
        : "r"(a0), "r"(a1), "r"(a2), "r"(a3), "r"(b0), "r"(b1));
}

// ---------------------------------------------------------------------------
// K0a: quantize f_conv_w to fp16, ic-pair packed, k = tap*64 + ic.
// ---------------------------------------------------------------------------
__global__ void weight_split_kernel(const float* __restrict__ wgt) {
    int idx = blockIdx.x * blockDim.x + threadIdx.x;   // over 9*32*576
    if (idx >= 9 * 32 * OCF) return;
    int oc = idx % OCF;
    int tmp = idx / OCF;
    int icp = tmp & 31;
    int s = tmp >> 5;
    float w0 = wgt[oc * KTOT + (2 * icp) * 9 + s];
    float w1 = wgt[oc * KTOT + (2 * icp + 1) * 9 + s];
    g_wh[idx] = pack_f16(__float2half(w0), __float2half(w1));
}

// ---------------------------------------------------------------------------
// K0b: pack small conv weights (p_conv 18 oc + m_conv 9 oc, pad to 32).
// ---------------------------------------------------------------------------
__global__ void weight_split_small_kernel(const float* __restrict__ p_w,
                                          const float* __restrict__ m_w) {
    int idx = blockIdx.x * blockDim.x + threadIdx.x;   // over 9*32*32
    if (idx >= 9 * 32 * 32) return;
    int oc = idx & 31;
    int tmp = idx >> 5;
    int icp = tmp & 31;
    int s = tmp >> 5;
    float w0 = 0.f, w1 = 0.f;
    if (oc < 18) {
        w0 = p_w[oc * KTOT + (2 * icp) * 9 + s];
        w1 = p_w[oc * KTOT + (2 * icp + 1) * 9 + s];
    } else if (oc < 27) {
        w0 = m_w[(oc - 18) * KTOT + (2 * icp) * 9 + s];
        w1 = m_w[(oc - 18) * KTOT + (2 * icp + 1) * 9 + s];
    }
    g_w1[idx] = pack_f16(__float2half(w0), __float2half(w1));
}

#define ROW_STRIDE 136
#define ICP_STRIDE (3 * ROW_STRIDE)   // 408

// ---------------------------------------------------------------------------
// K1: offset(18) + mask(9, sigmoid) conv via fp16 2-MMA-split tensor cores.
// Exact-A split kept here: this kernel produces COORDINATES.
// ---------------------------------------------------------------------------
#define SB1_STRIDE 40

__global__ __launch_bounds__(128) void conv_small_mma_kernel(
        const float* __restrict__ in,
        const float* __restrict__ p_b,
        const float* __restrict__ m_b) {
    const int bh = blockIdx.x;
    const int b = bh >> 7;
    const int h = bh & 127;
    const int tid = threadIdx.x;
    const int warp = tid >> 5;                // 0..3
    const int lane = tid & 31;
    const int g = lane >> 2;                  // 0..7
    const int t = lane & 3;                   // 0..3
    const int px0 = warp * 32;

    __shared__ __align__(16) uint32_t sAh[8 * ICP_STRIDE];
    __shared__ __align__(16) uint32_t sAl[8 * ICP_STRIDE];
    __shared__ __align__(16) uint32_t sB[72 * SB1_STRIDE];

    float acc[2][4][4];
#pragma unroll
    for (int mt = 0; mt < 2; mt++)
#pragma unroll
        for (int nt = 0; nt < 4; nt++)
#pragma unroll
            for (int q = 0; q < 4; q++) acc[mt][nt][q] = 0.f;

    const float* inb = in + b * C_ * HW;

    for (int chunk = 0; chunk < 4; chunk++) {
        __syncthreads();
        for (int idx = tid; idx < 8 * 3 * 130; idx += 128) {
            int icp = idx / 390;
            int rem = idx - icp * 390;
            int r = rem / 130;
            int cc = rem - r * 130;
            int gh = h + r - 1;
            int gw = cc - 1;
            float v0 = 0.f, v1 = 0.f;
            if ((unsigned)gh < 128u && (unsigned)gw < 128u) {
                const float* p = inb + (chunk * 16 + 2 * icp) * HW + gh * 128 + gw;
                v0 = p[0];
                v1 = p[HW];
            }
            __half h0 = __float2half(v0);
            __half h1 = __float2half(v1);
            __half l0 = __float2half(v0 - __half2float(h0));
            __half l1 = __float2half(v1 - __half2float(h1));
            sAh[icp * ICP_STRIDE + r * ROW_STRIDE + cc] = pack_f16(h0, h1);
            sAl[icp * ICP_STRIDE + r * ROW_STRIDE + cc] = pack_f16(l0, l1);
        }
        for (int idx = tid; idx < 72 * 8; idx += 128) {
            int row = idx >> 3;
            int q = idx & 7;
            int s = row >> 3;
            int icp = row & 7;
            const uint4* src = (const uint4*)(g_w1 + (s * 32 + chunk * 8 + icp) * 32);
            *(uint4*)(sB + row * SB1_STRIDE + q * 4) = src[q];
        }
        __syncthreads();

#pragma unroll
        for (int s = 0; s < 9; s++) {
            const int r = s / 3;
            const int dw = s - 3 * r;

            uint32_t ah[2][4], al[2][4];
#pragma unroll
            for (int mt = 0; mt < 2; mt++) {
                int cb = px0 + mt * 16 + g + dw;
                int base_lo = t * ICP_STRIDE + r * ROW_STRIDE + cb;
                int base_hi = (t + 4) * ICP_STRIDE + r * ROW_STRIDE + cb;
                ah[mt][0] = sAh[base_lo];
                ah[mt][1] = sAh[base_lo + 8];
                ah[mt][2] = sAh[base_hi];
                ah[mt][3] = sAh[base_hi + 8];
                al[mt][0] = sAl[base_lo];
                al[mt][1] = sAl[base_lo + 8];
                al[mt][2] = sAl[base_hi];
                al[mt][3] = sAl[base_hi + 8];
            }

            const int rb0 = (s * 8 + t) * SB1_STRIDE + g;
            const int rb1 = (s * 8 + t + 4) * SB1_STRIDE + g;
#pragma unroll
            for (int nt = 0; nt < 4; nt++) {
                uint32_t b0 = sB[rb0 + nt * 8];
                uint32_t b1 = sB[rb1 + nt * 8];
#pragma unroll
                for (int mt = 0; mt < 2; mt++) {
                    float* a = acc[mt][nt];
                    mma_f16(a, ah[mt][0], ah[mt][1], ah[mt][2], ah[mt][3], b0, b1);
                    mma_f16(a, al[mt][0], al[mt][1], al[mt][2], al[mt][3], b0, b1);
                }
            }
        }
    }

    // epilogue: direct scattered stores (27 live ocs)
#pragma unroll
    for (int nt = 0; nt < 4; nt++) {
#pragma unroll
        for (int q2 = 0; q2 < 2; q2++) {
            int oc = nt * 8 + 2 * t + q2;
            bool is_off = oc < 18;
            bool is_m = (oc >= 18) && (oc < 27);
            float bv = is_off ? __ldg(&p_b[oc]) : (is_m ? __ldg(&m_b[oc - 18]) : 0.f);
#pragma unroll
            for (int mt = 0; mt < 2; mt++) {
#pragma unroll
                for (int ph = 0; ph < 2; ph++) {
                    float v = acc[mt][nt][ph * 2 + q2] + bv;
                    int px = px0 + mt * 16 + g + ph * 8;
                    if (is_off)
                        g_off[((b * 18 + oc) * 128 + h) * 128 + px] = v;
                    else if (is_m)
                        g_m[((b * 9 + (oc - 18)) * 128 + h) * 128 + px] =
                            1.f / (1.f + expf(-v));
                }
            }
        }
    }
}

// ---------------------------------------------------------------------------
// K_samp: per (b,h,w,t) sampling table.
// ---------------------------------------------------------------------------
__global__ __launch_bounds__(256) void samp_table_kernel() {
    const int bh = blockIdx.x;
    const int b = bh >> 7;
    const int h = bh & 127;
    const int tid = threadIdx.x;

    for (int item = tid; item < 9 * 128; item += 256) {
        int t = item >> 7;
        int w = item & 127;
        int i = t / 3, j = t - 3 * i;
        int hp = (i == 0) ? h - 1 : h;
        int ip = (i == 0) ? 2 : i - 1;
        int wp = (j == 0) ? w - 1 : w;
        int jp = (j == 0) ? 2 : j - 1;
        uint32_t pc = 0;
        float4 g4 = make_float4(0.f, 0.f, 0.f, 0.f);
        if (hp >= 0 && wp >= 0) {
            int k = ip * 3 + jp;
            float dxk = (float)(ip - 1);
            float dyk = (float)(jp - 1);
            int obase = ((b * 18 + k) * 128 + hp) * 128 + wp;
            float ox = g_off[obase];
            float oy = g_off[obase + 9 * HW];
            float px = (float)(hp + 1) + dxk + ox;
            float py = (float)(wp + 1) + dyk + oy;
            float fx = floorf(px), fy = floorf(py);
            float ltx = fminf(fmaxf(fx, 0.f), 129.f);
            float lty = fminf(fmaxf(fy, 0.f), 129.f);
            float rbx = fminf(fmaxf(fx + 1.f, 0.f), 129.f);
            float rby = fminf(fmaxf(fy + 1.f, 0.f), 129.f);
            float pxc = fminf(fmaxf(px, 0.f), 129.f);
            float pyc = fminf(fmaxf(py, 0.f), 129.f);
            float gxl = 1.f + (ltx - pxc);
            float gxr = 1.f - (rbx - pxc);
            float gyl = 1.f + (lty - pyc);
            float gyr = 1.f - (rby - pyc);
            float mv = g_m[((b * 9 + k) * 128 + hp) * 128 + wp];
            uint32_t axs = (uint32_t)(int)ltx;     // 0..129
            uint32_t ays = (uint32_t)(int)lty;
            uint32_t bxs = (uint32_t)(int)rbx;
            uint32_t bys = (uint32_t)(int)rby;
            pc = axs | (ays << 8) | (bxs << 16) | (bys << 24);
            g4 = make_float4(gxl * gyl * mv, gxr * gyr * mv,
                             gxl * gyr * mv, gxr * gyl * mv);
        }
        g_tabc[bh * 1152 + t * 128 + w] = pc;
        g_tabg[bh * 1152 + t * 128 + w] = g4;
    }
}

// ---------------------------------------------------------------------------
// K2-fused: psff conv as PLAIN fp16 single-MMA tensor-core implicit GEMM +
// deformable sampling reduction.
// NEW vs R15/R16: A-lo correction MMA dropped (A quantized straight to fp16).
// Per warp per tap: 18 MMAs (was 36), 8 A LDS (was 16), 18 B LDS.
// Error budget: A-quant ~2.4e-4 + B-quant 2.4e-4 in quadrature ~3.4e-4.
// Grid: (8 oc-tiles of 72, 512 bh rows). 128 threads, warp tile 32px x 72oc.
// ---------------------------------------------------------------------------
#define SB_STRIDE 72
#define SP_STRIDE 132

__global__ __launch_bounds__(128, 4) void conv_fused_kernel(
        const float* __restrict__ in,
        const float* __restrict__ bias,
        const float* __restrict__ x,
        float* __restrict__ out) {
    const int oc0 = blockIdx.x * 72;
    const int bh = blockIdx.y;
    const int b = bh >> 7;
    const int h = bh & 127;
    const int tid = threadIdx.x;
    const int warp = tid >> 5;                // 0..3
    const int lane = tid & 31;
    const int g = lane >> 2;                  // 0..7
    const int t = lane & 3;                   // 0..3
    const int px0 = warp * 32;

    // buffer: max(sA 3264 + sB 5184 = 8448 u32, sP 9504 u32) = 37.1 KB
    __shared__ __align__(16) uint32_t sBuf[9504];
    uint32_t* sA = sBuf;
    uint32_t* sB = sBuf + 8 * ICP_STRIDE;     // 3264
    float* sP = (float*)sBuf;

    float acc[2][9][4];
#pragma unroll
    for (int mt = 0; mt < 2; mt++)
#pragma unroll
        for (int nt = 0; nt < 9; nt++)
#pragma unroll
            for (int q = 0; q < 4; q++) acc[mt][nt][q] = 0.f;

    const float* inb = in + b * C_ * HW;

    for (int chunk = 0; chunk < 4; chunk++) {
        __syncthreads();
        // stage A: 16 ics as 8 ic-pairs, fp16 (hi only), 3 rows x 130 cols
        for (int idx = tid; idx < 8 * 3 * 130; idx += 128) {
            int icp = idx / 390;
            int rem = idx - icp * 390;
            int r = rem / 130;
            int cc = rem - r * 130;
            int gh = h + r - 1;
            int gw = cc - 1;
            float v0 = 0.f, v1 = 0.f;
            if ((unsigned)gh < 128u && (unsigned)gw < 128u) {
                const float* p = inb + (chunk * 16 + 2 * icp) * HW + gh * 128 + gw;
                v0 = p[0];
                v1 = p[HW];
            }
            sA[icp * ICP_STRIDE + r * ROW_STRIDE + cc] =
                pack_f16(__float2half(v0), __float2half(v1));
        }
        // stage B: 72 rows (s*8 + icp) x 72 u32, vectorized uint4 copy
        for (int idx = tid; idx < 72 * 18; idx += 128) {
            int row = idx / 18;
            int q = idx - row * 18;
            int s = row >> 3;
            int icp = row & 7;
            const uint4* src = (const uint4*)(g_wh + (s * 32 + chunk * 8 + icp) * OCF + oc0);
            *(uint4*)(sB + row * SB_STRIDE + q * 4) = src[q];
        }
        __syncthreads();

#pragma unroll
        for (int s = 0; s < 9; s++) {
            const int r = s / 3;
            const int dw = s - 3 * r;

            uint32_t ah[2][4];
#pragma unroll
            for (int mt = 0; mt < 2; mt++) {
                int cb = px0 + mt * 16 + g + dw;
                int base_lo = t * ICP_STRIDE + r * ROW_STRIDE + cb;
                int base_hi = (t + 4) * ICP_STRIDE + r * ROW_STRIDE + cb;
                ah[mt][0] = sA[base_lo];
                ah[mt][1] = sA[base_lo + 8];
                ah[mt][2] = sA[base_hi];
                ah[mt][3] = sA[base_hi + 8];
            }

            const int rb0 = (s * 8 + t) * SB_STRIDE + g;
            const int rb1 = (s * 8 + t + 4) * SB_STRIDE + g;
#pragma unroll
            for (int ntg = 0; ntg < 3; ntg++) {
                uint32_t bhr[3][2];
#pragma unroll
                for (int u = 0; u < 3; u++) {
                    int col = (ntg * 3 + u) * 8;
                    bhr[u][0] = sB[rb0 + col];
                    bhr[u][1] = sB[rb1 + col];
                }
#pragma unroll
                for (int u = 0; u < 3; u++) {
#pragma unroll
                    for (int mt = 0; mt < 2; mt++) {
                        mma_f16(acc[mt][ntg * 3 + u],
                                ah[mt][0], ah[mt][1], ah[mt][2], ah[mt][3],
                                bhr[u][0], bhr[u][1]);
                    }
                }
            }
        }
    }

    // ---- epilogue phase 1: accumulators (+bias) -> sP[oc_local][px] ----
    __syncthreads();
#pragma unroll
    for (int nt = 0; nt < 9; nt++) {
        int oc_l = nt * 8 + 2 * t;
        float bva = __ldg(&bias[oc0 + oc_l]);
        float bvb = __ldg(&bias[oc0 + oc_l + 1]);
#pragma unroll
        for (int mt = 0; mt < 2; mt++) {
            int px = px0 + mt * 16 + g;
            sP[oc_l * SP_STRIDE + px]           = acc[mt][nt][0] + bva;
            sP[(oc_l + 1) * SP_STRIDE + px]     = acc[mt][nt][1] + bvb;
            sP[oc_l * SP_STRIDE + px + 8]       = acc[mt][nt][2] + bva;
            sP[(oc_l + 1) * SP_STRIDE + px + 8] = acc[mt][nt][3] + bvb;
        }
    }
    __syncthreads();

    // ---- epilogue phase 2: sampling reduction, 8 channels per thread ----
    const int w = tid;                         // 0..127
    const int c0 = blockIdx.x << 3;            // global channel base
    const float* xb = x + (size_t)(b * C_ + c0) * HW;

    float val[8] = {0.f, 0.f, 0.f, 0.f, 0.f, 0.f, 0.f, 0.f};

#pragma unroll
    for (int tt = 0; tt < 9; tt++) {
        uint32_t pc = g_tabc[bh * 1152 + tt * 128 + w];
        float4 g4 = g_tabg[bh * 1152 + tt * 128 + w];
        int ax = (int)(pc & 255u) - 1;
        int ay = (int)((pc >> 8) & 255u) - 1;
        int bx = (int)((pc >> 16) & 255u) - 1;
        int by = (int)(pc >> 24) - 1;
        bool vax = (unsigned)ax < 128u, vay = (unsigned)ay < 128u;
        bool vbx = (unsigned)bx < 128u, vby = (unsigned)by < 128u;
        int id0 = ax * 128 + ay;   // lt
        int id1 = bx * 128 + by;   // rb
        int id2 = ax * 128 + by;   // lb
        int id3 = bx * 128 + ay;   // rt
        const float* ps = &sP[tt * SP_STRIDE + w];
#pragma unroll
        for (int c = 0; c < 8; c++) {
            const float* xpl = xb + (size_t)c * HW;
            float s = 0.f;
            if (vax && vay) s += g4.x * __ldg(xpl + id0);
            if (vbx && vby) s += g4.y * __ldg(xpl + id1);
            if (vax && vby) s += g4.z * __ldg(xpl + id2);
            if (vbx && vay) s += g4.w * __ldg(xpl + id3);
            val[c] += s * ps[c * 9 * SP_STRIDE];
        }
    }

    float* ob = out + (size_t)(b * C_ + c0) * HW + h * 128 + w;
#pragma unroll
    for (int c = 0; c < 8; c++)
        ob[(size_t)c * HW] = val[c];
}

// ---------------------------------------------------------------------------
extern "C" void kernel_launch(void* const* d_in, const int* in_sizes, int n_in,
                              void* d_out, int out_size) {
    const float* feature_size    = (const float*)d_in[0];
    const float* feature_context = (const float*)d_in[1];
    const float* x               = (const float*)d_in[2];
    const float* p_conv_w        = (const float*)d_in[3];
    const float* p_conv_b        = (const float*)d_in[4];
    const float* f_conv_w        = (const float*)d_in[5];
    const float* f_conv_b        = (const float*)d_in[6];
    const float* m_conv_w        = (const float*)d_in[7];
    const float* m_conv_b        = (const float*)d_in[8];
    float* out = (float*)d_out;

    // K0: quantize weights to fp16
    weight_split_kernel<<<(9 * 32 * OCF + 255) / 256, 256>>>(f_conv_w);
    weight_split_small_kernel<<<(9 * 32 * 32 + 255) / 256, 256>>>(p_conv_w, m_conv_w);

    // K1: offset(18) + mask(9, sigmoid) conv via tensor cores
    conv_small_mma_kernel<<<B_ * H_, 128>>>(feature_size, p_conv_b, m_conv_b);

    // K_samp: sampling tables from g_off/g_m
    samp_table_kernel<<<B_ * H_, 256>>>();

    // K2-fused: psff conv + sampling reduction -> out
    dim3 grid2(8, B_ * H_);
    conv_fused_kernel<<<grid2, 128>>>(feature_context, f_conv_b, x, out);
}